// round 4
// baseline (speedup 1.0000x reference)
#include <cuda_runtime.h>
#include <math.h>
#include <stdint.h>

// ---------------- problem constants ----------------
#define Bn   32
#define Ln   2048
#define Cn   32
#define PLn  16
#define Pp   128
#define Dd   64
#define Hh   256
#define Kk   512
#define NSEQ (Bn*Cn)        // 1024
#define NTOK (NSEQ*Pp)      // 131072
#define EPSF 1e-5f

// output layout (flattened reference return tuple, float32)
#define OFF_ZQ   ((size_t)2)
#define OFF_R    (OFF_ZQ + (size_t)NTOK*Dd)            // 8388610
#define OFF_IDX  (OFF_R + (size_t)Bn*Ln*Cn)            // 10485762
#define OFF_PERP (OFF_IDX + (size_t)NTOK)              // 10616834

// ---------------- device scratch (no allocs allowed) ----------------
__device__ float g_mean[NSEQ];
__device__ float g_std[NSEQ];
__device__ float g_z[(size_t)NTOK*Dd];      // encoder output z, 33.5 MB
__device__ int   g_counts[Kk];
__device__ float g_sq_partial[512];
__device__ float g_rec_partial[512];

// ---------------- kernel 1: RevIN stats + zero counts ----------------
__global__ __launch_bounds__(256) void pcv_revin(const float* __restrict__ x)
{
    int b = blockIdx.x;
    int t = threadIdx.x;
    int c = t & 31;
    int g = t >> 5;              // 8 row-groups
    if (b == 0) {
        for (int i = t; i < Kk; i += 256) g_counts[i] = 0;
    }
    float s = 0.f, s2 = 0.f;
    const float* xb = x + (size_t)b * Ln * Cn + c;
    for (int l = g; l < Ln; l += 8) {
        float v = xb[(size_t)l * Cn];
        s += v; s2 += v * v;
    }
    __shared__ float sh_s[256], sh_q[256];
    sh_s[t] = s; sh_q[t] = s2;
    __syncthreads();
    if (g == 0) {
        float ss = 0.f, qq = 0.f;
#pragma unroll
        for (int i = 0; i < 8; i++) { ss += sh_s[i * 32 + c]; qq += sh_q[i * 32 + c]; }
        float mean = ss * (1.0f / Ln);
        float var  = qq * (1.0f / Ln) - mean * mean;
        g_mean[b * 32 + c] = mean;
        g_std [b * 32 + c] = sqrtf(var + EPSF);
    }
}

// 64x64 row-matmul helper: acc[d] = bias[d] + sum_k hrow[k]*w[k*64+d]
__device__ __forceinline__ void mm64(const float* __restrict__ hrow,
                                     const float* __restrict__ w,
                                     const float* __restrict__ bias,
                                     float* acc)
{
#pragma unroll
    for (int d = 0; d < 64; d++) acc[d] = bias[d];
#pragma unroll 4
    for (int k = 0; k < 64; k++) {
        float hk = hrow[k];
        const float4* w4 = reinterpret_cast<const float4*>(w + k * 64);
#pragma unroll
        for (int d4 = 0; d4 < 16; d4++) {
            float4 ww = w4[d4];
            acc[d4 * 4 + 0] += hk * ww.x;
            acc[d4 * 4 + 1] += hk * ww.y;
            acc[d4 * 4 + 2] += hk * ww.z;
            acc[d4 * 4 + 3] += hk * ww.w;
        }
    }
}

// ---------------- kernel 2: encoder (one block per sequence) ----------------
// smem layout (floats):
//   s_h   : 128*65                (padded, private per-thread rows)
//   s_buf : 32768, reused:
//     attn stage: s_q(128*65) | s_k(128*64) | s_v(128*64) | s_wt(64*64)
//     ffn  stage: s_w1t(256*64 transposed) | s_w2(256*64)
#define ENC_SMEM ((128*65 + 32768) * 4)

__global__ __launch_bounds__(128) void pcv_encoder(
    const float* __restrict__ x,
    const float* __restrict__ revin_w, const float* __restrict__ revin_b,
    const float* __restrict__ inp_W,   const float* __restrict__ inp_b,
    const float* __restrict__ Wq, const float* __restrict__ bq,
    const float* __restrict__ Wk, const float* __restrict__ bk,
    const float* __restrict__ Wv, const float* __restrict__ bv,
    const float* __restrict__ Wo, const float* __restrict__ bo,
    const float* __restrict__ ln1_g, const float* __restrict__ ln1_b,
    const float* __restrict__ W1, const float* __restrict__ b1,
    const float* __restrict__ W2, const float* __restrict__ b2,
    const float* __restrict__ ln2_g, const float* __restrict__ ln2_b)
{
    extern __shared__ float sm[];
    float* s_h   = sm;
    float* s_buf = sm + 128 * 65;
    float* s_q   = s_buf;
    float* s_k   = s_buf + 128 * 65;
    float* s_v   = s_k + 128 * 64;
    float* s_wt  = s_v + 128 * 64;
    float* s_w1t = s_buf;
    float* s_w2  = s_buf + 64 * 256;

    int n = blockIdx.x;
    int b = n >> 5, c = n & 31;
    int p = threadIdx.x;

    float mean = g_mean[n];
    float istd = 1.0f / g_std[n];
    float rw = revin_w[c], rb = revin_b[c];

    // --- load inp_W (16x64) ---
    for (int i = p; i < 16 * 64; i += 128) s_wt[i] = inp_W[i];
    __syncthreads();

    // --- patch embed: h row ---
    float acc[64];
#pragma unroll
    for (int d = 0; d < 64; d++) acc[d] = inp_b[d];
    const float* xp = x + ((size_t)b * Ln + (size_t)p * PLn) * Cn + c;
#pragma unroll
    for (int j = 0; j < 16; j++) {
        float xv = (xp[(size_t)j * Cn] - mean) * istd * rw + rb;
        const float4* w4 = reinterpret_cast<const float4*>(s_wt + j * 64);
#pragma unroll
        for (int d4 = 0; d4 < 16; d4++) {
            float4 ww = w4[d4];
            acc[d4 * 4 + 0] += xv * ww.x;
            acc[d4 * 4 + 1] += xv * ww.y;
            acc[d4 * 4 + 2] += xv * ww.z;
            acc[d4 * 4 + 3] += xv * ww.w;
        }
    }
#pragma unroll
    for (int d = 0; d < 64; d++) s_h[p * 65 + d] = acc[d];
    __syncthreads();

    // --- Q ---
    for (int i = p; i < 4096; i += 128) s_wt[i] = Wq[i];
    __syncthreads();
    mm64(s_h + p * 65, s_wt, bq, acc);
#pragma unroll
    for (int d = 0; d < 64; d++) s_q[p * 65 + d] = acc[d];
    __syncthreads();
    // --- K ---
    for (int i = p; i < 4096; i += 128) s_wt[i] = Wk[i];
    __syncthreads();
    mm64(s_h + p * 65, s_wt, bk, acc);
#pragma unroll
    for (int d = 0; d < 64; d++) s_k[p * 64 + d] = acc[d];
    __syncthreads();
    // --- V ---
    for (int i = p; i < 4096; i += 128) s_wt[i] = Wv[i];
    __syncthreads();
    mm64(s_h + p * 65, s_wt, bv, acc);
#pragma unroll
    for (int d = 0; d < 64; d++) s_v[p * 64 + d] = acc[d];
    __syncthreads();
    // --- Wo into s_wt (also guarantees k/v/q fully visible) ---
    for (int i = p; i < 4096; i += 128) s_wt[i] = Wo[i];
    __syncthreads();

    // --- attention (online softmax per head) ---
    float arow[64];
#pragma unroll
    for (int hh = 0; hh < 4; hh++) {
        float qh[16];
#pragma unroll
        for (int j = 0; j < 16; j++) qh[j] = s_q[p * 65 + hh * 16 + j];
        float m = -1e30f, lsum = 0.f;
        float oac[16];
#pragma unroll
        for (int j = 0; j < 16; j++) oac[j] = 0.f;
        for (int pk = 0; pk < 128; pk++) {
            const float4* kr = reinterpret_cast<const float4*>(s_k + pk * 64 + hh * 16);
            float s = 0.f;
#pragma unroll
            for (int j4 = 0; j4 < 4; j4++) {
                float4 kv = kr[j4];
                s += qh[j4 * 4 + 0] * kv.x + qh[j4 * 4 + 1] * kv.y
                   + qh[j4 * 4 + 2] * kv.z + qh[j4 * 4 + 3] * kv.w;
            }
            s *= 0.25f;   // 1/sqrt(16)
            float mn   = fmaxf(m, s);
            float corr = __expf(m - mn);
            float w    = __expf(s - mn);
            lsum = lsum * corr + w;
            const float4* vr = reinterpret_cast<const float4*>(s_v + pk * 64 + hh * 16);
#pragma unroll
            for (int j4 = 0; j4 < 4; j4++) {
                float4 vv = vr[j4];
                oac[j4 * 4 + 0] = oac[j4 * 4 + 0] * corr + w * vv.x;
                oac[j4 * 4 + 1] = oac[j4 * 4 + 1] * corr + w * vv.y;
                oac[j4 * 4 + 2] = oac[j4 * 4 + 2] * corr + w * vv.z;
                oac[j4 * 4 + 3] = oac[j4 * 4 + 3] * corr + w * vv.w;
            }
            m = mn;
        }
        float inv = 1.0f / lsum;
#pragma unroll
        for (int j = 0; j < 16; j++) arow[hh * 16 + j] = oac[j] * inv;
    }

    // stash attn output in own q row (private), project with Wo
#pragma unroll
    for (int j = 0; j < 64; j++) s_q[p * 65 + j] = arow[j];
    mm64(s_q + p * 65, s_wt, bo, acc);

    // --- residual + LN1 ---
    float hn[64];
    float msum = 0.f;
#pragma unroll
    for (int d = 0; d < 64; d++) { hn[d] = s_h[p * 65 + d] + acc[d]; msum += hn[d]; }
    float mu = msum * (1.0f / 64);
    float vs = 0.f;
#pragma unroll
    for (int d = 0; d < 64; d++) { float df = hn[d] - mu; vs += df * df; }
    float rs = 1.0f / sqrtf(vs * (1.0f / 64) + EPSF);
#pragma unroll
    for (int d = 0; d < 64; d++) hn[d] = (hn[d] - mu) * rs * ln1_g[d] + ln1_b[d];

    __syncthreads();   // everyone done with s_q/s_k/s_v/s_wt
#pragma unroll
    for (int d = 0; d < 64; d++) s_h[p * 65 + d] = hn[d];

    // --- FFN weights: W1 transposed to [H][D], W2 as-is ---
    for (int i = p; i < 64 * 256; i += 128) {
        int j = i >> 8, k = i & 255;
        s_w1t[k * 64 + j] = W1[i];
    }
    for (int i = p; i < 256 * 64; i += 128) s_w2[i] = W2[i];
    __syncthreads();

#pragma unroll
    for (int d = 0; d < 64; d++) acc[d] = b2[d];
    for (int k = 0; k < 256; k++) {
        const float4* w1c = reinterpret_cast<const float4*>(s_w1t + k * 64);
        float f = b1[k];
#pragma unroll
        for (int j4 = 0; j4 < 16; j4++) {
            float4 ww = w1c[j4];
            f += hn[j4 * 4 + 0] * ww.x + hn[j4 * 4 + 1] * ww.y
               + hn[j4 * 4 + 2] * ww.z + hn[j4 * 4 + 3] * ww.w;
        }
        f = fmaxf(f, 0.f);
        const float4* w2r = reinterpret_cast<const float4*>(s_w2 + k * 64);
#pragma unroll
        for (int d4 = 0; d4 < 16; d4++) {
            float4 ww = w2r[d4];
            acc[d4 * 4 + 0] += f * ww.x;
            acc[d4 * 4 + 1] += f * ww.y;
            acc[d4 * 4 + 2] += f * ww.z;
            acc[d4 * 4 + 3] += f * ww.w;
        }
    }

    // --- residual + LN2 -> z ---
    msum = 0.f;
#pragma unroll
    for (int d = 0; d < 64; d++) { acc[d] += hn[d]; msum += acc[d]; }
    mu = msum * (1.0f / 64);
    vs = 0.f;
#pragma unroll
    for (int d = 0; d < 64; d++) { float df = acc[d] - mu; vs += df * df; }
    rs = 1.0f / sqrtf(vs * (1.0f / 64) + EPSF);
    float zr[64];
#pragma unroll
    for (int d = 0; d < 64; d++) zr[d] = (acc[d] - mu) * rs * ln2_g[d] + ln2_b[d];
    float4* zg = reinterpret_cast<float4*>(g_z + ((size_t)n * 128 + p) * 64);
#pragma unroll
    for (int d4 = 0; d4 < 16; d4++)
        zg[d4] = make_float4(zr[d4 * 4], zr[d4 * 4 + 1], zr[d4 * 4 + 2], zr[d4 * 4 + 3]);
}

// ---------------- kernel 3: quantizer ----------------
#define QNT_SMEM ((Kk*Dd + Kk) * 4)

__global__ __launch_bounds__(256) void pcv_quant(const float* __restrict__ codebook,
                                                 float* __restrict__ out)
{
    extern __shared__ float sm[];
    float* s_cb = sm;
    float* s_e2 = sm + Kk * Dd;
    __shared__ float red[256];
    int tid = threadIdx.x;
    for (int i = tid; i < Kk * Dd; i += 256) s_cb[i] = codebook[i];
    __syncthreads();
    for (int k = tid; k < Kk; k += 256) {
        const float* cr = s_cb + k * 64;
        float s = 0.f;
#pragma unroll 8
        for (int j = 0; j < 64; j++) s += cr[j] * cr[j];
        s_e2[k] = s;
    }
    __syncthreads();

    int t = blockIdx.x * 256 + tid;
    const float4* zg = reinterpret_cast<const float4*>(g_z + (size_t)t * 64);
    float zr[64];
#pragma unroll
    for (int j4 = 0; j4 < 16; j4++) {
        float4 v = zg[j4];
        zr[j4 * 4] = v.x; zr[j4 * 4 + 1] = v.y; zr[j4 * 4 + 2] = v.z; zr[j4 * 4 + 3] = v.w;
    }
    float z2 = 0.f;
#pragma unroll
    for (int j = 0; j < 64; j++) z2 += zr[j] * zr[j];

    float best = 3.4e38f;
    int bi = 0;
    for (int k = 0; k < Kk; k++) {
        const float4* cr = reinterpret_cast<const float4*>(s_cb + k * 64);
        float dot = 0.f;
#pragma unroll
        for (int j4 = 0; j4 < 16; j4++) {
            float4 cv = cr[j4];
            dot += zr[j4 * 4 + 0] * cv.x;
            dot += zr[j4 * 4 + 1] * cv.y;
            dot += zr[j4 * 4 + 2] * cv.z;
            dot += zr[j4 * 4 + 3] * cv.w;
        }
        // replicate reference rounding: (z2 + e2) - 2*ze, no fusion
        float d = __fadd_rn(__fadd_rn(z2, s_e2[k]), -__fmul_rn(2.0f, dot));
        if (d < best) { best = d; bi = k; }
    }

    // write z_q_st (== codebook[bi]) and index
    float2* zqo = reinterpret_cast<float2*>(out + OFF_ZQ + (size_t)t * 64);
    const float2* cb2 = reinterpret_cast<const float2*>(s_cb + bi * 64);
#pragma unroll
    for (int j = 0; j < 32; j++) zqo[j] = cb2[j];
    out[OFF_IDX + t] = (float)bi;
    atomicAdd(&g_counts[bi], 1);

    // deterministic per-block sum of squared distances
    red[tid] = best;
    __syncthreads();
    for (int s = 128; s > 0; s >>= 1) {
        if (tid < s) red[tid] += red[tid + s];
        __syncthreads();
    }
    if (tid == 0) g_sq_partial[blockIdx.x] = red[0];
}

// ---------------- kernel 4: decoder + denorm + rec-loss partials ----------------
#define DEC_SMEM ((256*64 + 256*16 + 64*16) * 4)

__global__ __launch_bounds__(256) void pcv_dec(
    const float* __restrict__ x,
    const float* __restrict__ revin_w, const float* __restrict__ revin_b,
    const float* __restrict__ dW1, const float* __restrict__ db1,
    const float* __restrict__ dW2, const float* __restrict__ db2,
    const float* __restrict__ dWr, const float* __restrict__ dbr,
    const float* __restrict__ lng, const float* __restrict__ lnb,
    float* __restrict__ out)
{
    extern __shared__ float sm[];
    float* s_w1t = sm;               // [256][64] transposed
    float* s_w2  = sm + 256 * 64;    // [256][16]
    float* s_wr  = s_w2 + 256 * 16;  // [64][16]
    __shared__ float red[256];
    int tid = threadIdx.x;
    for (int i = tid; i < 64 * 256; i += 256) {
        int j = i >> 8, k = i & 255;
        s_w1t[k * 64 + j] = dW1[i];
    }
    for (int i = tid; i < 256 * 16; i += 256) s_w2[i] = dW2[i];
    for (int i = tid; i < 64 * 16; i += 256)  s_wr[i] = dWr[i];
    __syncthreads();

    int t = blockIdx.x * 256 + tid;
    int n = t >> 7, p = t & 127, b = n >> 5, c = n & 31;

    float zq[64];
    const float2* zg = reinterpret_cast<const float2*>(out + OFF_ZQ + (size_t)t * 64);
#pragma unroll
    for (int j = 0; j < 32; j++) { float2 v = zg[j]; zq[2 * j] = v.x; zq[2 * j + 1] = v.y; }

    float y[16];
#pragma unroll
    for (int i = 0; i < 16; i++) y[i] = db2[i];
    for (int k = 0; k < 256; k++) {
        const float4* w1c = reinterpret_cast<const float4*>(s_w1t + k * 64);
        float f = db1[k];
#pragma unroll
        for (int j4 = 0; j4 < 16; j4++) {
            float4 w = w1c[j4];
            f += zq[j4 * 4 + 0] * w.x + zq[j4 * 4 + 1] * w.y
               + zq[j4 * 4 + 2] * w.z + zq[j4 * 4 + 3] * w.w;
        }
        f = fmaxf(f, 0.f);
        const float4* w2r = reinterpret_cast<const float4*>(s_w2 + k * 16);
#pragma unroll
        for (int i4 = 0; i4 < 4; i4++) {
            float4 w = w2r[i4];
            y[i4 * 4 + 0] += f * w.x;
            y[i4 * 4 + 1] += f * w.y;
            y[i4 * 4 + 2] += f * w.z;
            y[i4 * 4 + 3] += f * w.w;
        }
    }
#pragma unroll
    for (int i = 0; i < 16; i++) y[i] += dbr[i];
#pragma unroll 8
    for (int j = 0; j < 64; j++) {
        float zj = zq[j];
        const float4* wr4 = reinterpret_cast<const float4*>(s_wr + j * 16);
#pragma unroll
        for (int i4 = 0; i4 < 4; i4++) {
            float4 w = wr4[i4];
            y[i4 * 4 + 0] += zj * w.x;
            y[i4 * 4 + 1] += zj * w.y;
            y[i4 * 4 + 2] += zj * w.z;
            y[i4 * 4 + 3] += zj * w.w;
        }
    }

    // LN over PL=16
    float mu = 0.f;
#pragma unroll
    for (int i = 0; i < 16; i++) mu += y[i];
    mu *= (1.0f / 16);
    float var = 0.f;
#pragma unroll
    for (int i = 0; i < 16; i++) { float d = y[i] - mu; var += d * d; }
    var *= (1.0f / 16);
    float rs = 1.0f / sqrtf(var + EPSF);

    // RevIN denorm + squared error
    float stdv = g_std[n], meanv = g_mean[n];
    float wpe = revin_w[c] + 1e-10f;  // EPS*EPS
    float rbc = revin_b[c];
    float local = 0.f;
    size_t base = ((size_t)b * Ln + (size_t)p * 16) * Cn + c;
#pragma unroll
    for (int i = 0; i < 16; i++) {
        float rec = (y[i] - mu) * rs * lng[i] + lnb[i];
        float rv = (rec - rbc) / wpe * stdv + meanv;
        out[OFF_R + base + (size_t)i * Cn] = rv;
        float dx = x[base + (size_t)i * Cn] - rv;
        local += dx * dx;
    }
    red[tid] = local;
    __syncthreads();
    for (int s = 128; s > 0; s >>= 1) {
        if (tid < s) red[tid] += red[tid + s];
        __syncthreads();
    }
    if (tid == 0) g_rec_partial[blockIdx.x] = red[0];
}

// ---------------- kernel 5: finalize scalars ----------------
__global__ void pcv_final(float* __restrict__ out)
{
    if (threadIdx.x == 0 && blockIdx.x == 0) {
        float sq = 0.f;
        for (int i = 0; i < 512; i++) sq += g_sq_partial[i];
        float recs = 0.f;
        for (int i = 0; i < 512; i++) recs += g_rec_partial[i];
        float mse = sq * (1.0f / 8388608.0f);            // mean over B*C*P*D
        float cluster = mse + 0.25f * mse;               // codebook + BETA*commitment
        float rec_loss = recs * (1.0f / 2097152.0f);     // mean over B*L*C
        out[0] = rec_loss + 0.2f * cluster;
        out[1] = rec_loss;
        float tot = 0.f;
        for (int k = 0; k < Kk; k++) tot += (float)g_counts[k];
        float inv = 1.0f / (tot + EPSF);
        float ent = 0.f;
        for (int k = 0; k < Kk; k++) {
            float pr = (float)g_counts[k] * inv;
            ent += pr * logf(pr + EPSF);
        }
        out[OFF_PERP] = expf(-ent);
    }
}

// ---------------- launch ----------------
extern "C" void kernel_launch(void* const* d_in, const int* in_sizes, int n_in,
                              void* d_out, int out_size)
{
    const float* x       = (const float*)d_in[0];
    const float* revin_w = (const float*)d_in[1];
    const float* revin_b = (const float*)d_in[2];
    const float* inp_W   = (const float*)d_in[3];
    const float* inp_b   = (const float*)d_in[4];
    const float* Wq = (const float*)d_in[5];  const float* bq = (const float*)d_in[6];
    const float* Wk = (const float*)d_in[7];  const float* bk = (const float*)d_in[8];
    const float* Wv = (const float*)d_in[9];  const float* bv = (const float*)d_in[10];
    const float* Wo = (const float*)d_in[11]; const float* bo = (const float*)d_in[12];
    const float* ln1_g = (const float*)d_in[13]; const float* ln1_b = (const float*)d_in[14];
    const float* W1 = (const float*)d_in[15]; const float* b1 = (const float*)d_in[16];
    const float* W2 = (const float*)d_in[17]; const float* b2 = (const float*)d_in[18];
    const float* ln2_g = (const float*)d_in[19]; const float* ln2_b = (const float*)d_in[20];
    const float* codebook = (const float*)d_in[21];
    const float* dW1 = (const float*)d_in[22]; const float* db1 = (const float*)d_in[23];
    const float* dW2 = (const float*)d_in[24]; const float* db2 = (const float*)d_in[25];
    const float* dWr = (const float*)d_in[26]; const float* dbr = (const float*)d_in[27];
    const float* dlg = (const float*)d_in[28]; const float* dlb = (const float*)d_in[29];
    float* out = (float*)d_out;

    cudaFuncSetAttribute(pcv_encoder, cudaFuncAttributeMaxDynamicSharedMemorySize, ENC_SMEM);
    cudaFuncSetAttribute(pcv_quant,   cudaFuncAttributeMaxDynamicSharedMemorySize, QNT_SMEM);
    cudaFuncSetAttribute(pcv_dec,     cudaFuncAttributeMaxDynamicSharedMemorySize, DEC_SMEM);

    pcv_revin<<<Bn, 256>>>(x);
    pcv_encoder<<<NSEQ, 128, ENC_SMEM>>>(x, revin_w, revin_b, inp_W, inp_b,
                                         Wq, bq, Wk, bk, Wv, bv, Wo, bo,
                                         ln1_g, ln1_b, W1, b1, W2, b2, ln2_g, ln2_b);
    pcv_quant<<<NTOK / 256, 256, QNT_SMEM>>>(codebook, out);
    pcv_dec<<<NTOK / 256, 256, DEC_SMEM>>>(x, revin_w, revin_b,
                                           dW1, db1, dW2, db2, dWr, dbr, dlg, dlb, out);
    pcv_final<<<1, 32>>>(out);
}

// round 5
// speedup vs baseline: 1.2252x; 1.2252x over previous
#include <cuda_runtime.h>
#include <math.h>
#include <stdint.h>

// ---------------- problem constants ----------------
#define Bn   32
#define Ln   2048
#define Cn   32
#define PLn  16
#define Pp   128
#define Dd   64
#define Hh   256
#define Kk   512
#define NSEQ (Bn*Cn)        // 1024
#define NTOK (NSEQ*Pp)      // 131072
#define EPSF 1e-5f

// output layout (flattened reference return tuple, float32)
#define OFF_ZQ   ((size_t)2)
#define OFF_R    (OFF_ZQ + (size_t)NTOK*Dd)            // 8388610
#define OFF_IDX  (OFF_R + (size_t)Bn*Ln*Cn)            // 10485762
#define OFF_PERP (OFF_IDX + (size_t)NTOK)              // 10616834

// ---------------- device scratch ----------------
__device__ float g_mean[NSEQ];
__device__ float g_std[NSEQ];
__device__ float g_z[(size_t)NTOK*Dd];      // encoder output z
__device__ int   g_counts[Kk];
__device__ float g_sq_partial[512];
__device__ float g_rec_partial[512];
__device__ float g_rec[Kk*PLn];             // per-codeword decoded patch (post-LN)

// ---------------- kernel 1: RevIN stats + zero counts (unchanged math) ----------------
__global__ __launch_bounds__(256) void pcv_revin(const float* __restrict__ x)
{
    int b = blockIdx.x;
    int t = threadIdx.x;
    int c = t & 31;
    int g = t >> 5;
    if (b == 0) {
        for (int i = t; i < Kk; i += 256) g_counts[i] = 0;
    }
    float s = 0.f, s2 = 0.f;
    const float* xb = x + (size_t)b * Ln * Cn + c;
    for (int l = g; l < Ln; l += 8) {
        float v = xb[(size_t)l * Cn];
        s += v; s2 += v * v;
    }
    __shared__ float sh_s[256], sh_q[256];
    sh_s[t] = s; sh_q[t] = s2;
    __syncthreads();
    if (g == 0) {
        float ss = 0.f, qq = 0.f;
#pragma unroll
        for (int i = 0; i < 8; i++) { ss += sh_s[i * 32 + c]; qq += sh_q[i * 32 + c]; }
        float mean = ss * (1.0f / Ln);
        float var  = qq * (1.0f / Ln) - mean * mean;
        g_mean[b * 32 + c] = mean;
        g_std [b * 32 + c] = sqrtf(var + EPSF);
    }
}

// 64x64 row-matmul: acc[d] = bias[d] + sum_k hrow[k]*w[k*64+d]   (unchanged)
__device__ __forceinline__ void mm64(const float* __restrict__ hrow,
                                     const float* __restrict__ w,
                                     const float* __restrict__ bias,
                                     float* acc)
{
#pragma unroll
    for (int d = 0; d < 64; d++) acc[d] = bias[d];
#pragma unroll 4
    for (int k = 0; k < 64; k++) {
        float hk = hrow[k];
        const float4* w4 = reinterpret_cast<const float4*>(w + k * 64);
#pragma unroll
        for (int d4 = 0; d4 < 16; d4++) {
            float4 ww = w4[d4];
            acc[d4 * 4 + 0] += hk * ww.x;
            acc[d4 * 4 + 1] += hk * ww.y;
            acc[d4 * 4 + 2] += hk * ww.z;
            acc[d4 * 4 + 3] += hk * ww.w;
        }
    }
}

// ---------------- kernel 2: encoder (2 blocks/SM now; math bit-identical) ----------------
// smem: s_h 128*65 (private rows) | s_k 128*64 | s_v 128*64 | s_w 64*64  = 115200 B
#define ENC_SMEM ((128*65 + 128*64 + 128*64 + 64*64) * 4)

__global__ void __launch_bounds__(128, 2) pcv_encoder(
    const float* __restrict__ x,
    const float* __restrict__ revin_w, const float* __restrict__ revin_b,
    const float* __restrict__ inp_W,   const float* __restrict__ inp_b,
    const float* __restrict__ Wq, const float* __restrict__ bq,
    const float* __restrict__ Wk, const float* __restrict__ bk,
    const float* __restrict__ Wv, const float* __restrict__ bv,
    const float* __restrict__ Wo, const float* __restrict__ bo,
    const float* __restrict__ ln1_g, const float* __restrict__ ln1_b,
    const float* __restrict__ W1, const float* __restrict__ b1,
    const float* __restrict__ W2, const float* __restrict__ b2,
    const float* __restrict__ ln2_g, const float* __restrict__ ln2_b)
{
    extern __shared__ float sm[];
    float* s_h = sm;                  // 128*65, thread-private rows
    float* s_k = sm + 128 * 65;       // 128*64
    float* s_v = s_k + 128 * 64;      // 128*64
    float* s_w = s_v + 128 * 64;      // 64*64 weight staging

    int n = blockIdx.x;
    int b = n >> 5, c = n & 31;
    int p = threadIdx.x;

    float mean = g_mean[n];
    float istd = 1.0f / g_std[n];
    float rw = revin_w[c], rb = revin_b[c];

    // --- patch embed ---
    for (int i = p; i < 16 * 64; i += 128) s_w[i] = inp_W[i];
    __syncthreads();
    float acc[64];
#pragma unroll
    for (int d = 0; d < 64; d++) acc[d] = inp_b[d];
    const float* xp = x + ((size_t)b * Ln + (size_t)p * PLn) * Cn + c;
#pragma unroll
    for (int j = 0; j < 16; j++) {
        float xv = (xp[(size_t)j * Cn] - mean) * istd * rw + rb;
        const float4* w4 = reinterpret_cast<const float4*>(s_w + j * 64);
#pragma unroll
        for (int d4 = 0; d4 < 16; d4++) {
            float4 ww = w4[d4];
            acc[d4 * 4 + 0] += xv * ww.x;
            acc[d4 * 4 + 1] += xv * ww.y;
            acc[d4 * 4 + 2] += xv * ww.z;
            acc[d4 * 4 + 3] += xv * ww.w;
        }
    }
#pragma unroll
    for (int d = 0; d < 64; d++) s_h[p * 65 + d] = acc[d];
    __syncthreads();

    // --- Q (kept in registers) ---
    for (int i = p; i < 4096; i += 128) s_w[i] = Wq[i];
    __syncthreads();
    mm64(s_h + p * 65, s_w, bq, acc);
    float qreg[64];
#pragma unroll
    for (int d = 0; d < 64; d++) qreg[d] = acc[d];
    __syncthreads();
    // --- K ---
    for (int i = p; i < 4096; i += 128) s_w[i] = Wk[i];
    __syncthreads();
    mm64(s_h + p * 65, s_w, bk, acc);
#pragma unroll
    for (int d = 0; d < 64; d++) s_k[p * 64 + d] = acc[d];
    __syncthreads();
    // --- V ---
    for (int i = p; i < 4096; i += 128) s_w[i] = Wv[i];
    __syncthreads();
    mm64(s_h + p * 65, s_w, bv, acc);
#pragma unroll
    for (int d = 0; d < 64; d++) s_v[p * 64 + d] = acc[d];
    __syncthreads();
    // --- Wo (sync also publishes k/v) ---
    for (int i = p; i < 4096; i += 128) s_w[i] = Wo[i];
    __syncthreads();

    // --- attention (identical math to passing kernel) ---
    float arow[64];
#pragma unroll
    for (int hh = 0; hh < 4; hh++) {
        float qh[16];
#pragma unroll
        for (int j = 0; j < 16; j++) qh[j] = qreg[hh * 16 + j];
        float m = -1e30f, lsum = 0.f;
        float oac[16];
#pragma unroll
        for (int j = 0; j < 16; j++) oac[j] = 0.f;
        for (int pk = 0; pk < 128; pk++) {
            const float4* kr = reinterpret_cast<const float4*>(s_k + pk * 64 + hh * 16);
            float s = 0.f;
#pragma unroll
            for (int j4 = 0; j4 < 4; j4++) {
                float4 kv = kr[j4];
                s += qh[j4 * 4 + 0] * kv.x + qh[j4 * 4 + 1] * kv.y
                   + qh[j4 * 4 + 2] * kv.z + qh[j4 * 4 + 3] * kv.w;
            }
            s *= 0.25f;
            float mn   = fmaxf(m, s);
            float corr = __expf(m - mn);
            float w    = __expf(s - mn);
            lsum = lsum * corr + w;
            const float4* vr = reinterpret_cast<const float4*>(s_v + pk * 64 + hh * 16);
#pragma unroll
            for (int j4 = 0; j4 < 4; j4++) {
                float4 vv = vr[j4];
                oac[j4 * 4 + 0] = oac[j4 * 4 + 0] * corr + w * vv.x;
                oac[j4 * 4 + 1] = oac[j4 * 4 + 1] * corr + w * vv.y;
                oac[j4 * 4 + 2] = oac[j4 * 4 + 2] * corr + w * vv.z;
                oac[j4 * 4 + 3] = oac[j4 * 4 + 3] * corr + w * vv.w;
            }
            m = mn;
        }
        float inv = 1.0f / lsum;
#pragma unroll
        for (int j = 0; j < 16; j++) arow[hh * 16 + j] = oac[j] * inv;
    }

    // save h row into regs, stage arow through own (private) s_h row, project with Wo
    float hreg[64];
#pragma unroll
    for (int d = 0; d < 64; d++) hreg[d] = s_h[p * 65 + d];
#pragma unroll
    for (int d = 0; d < 64; d++) s_h[p * 65 + d] = arow[d];
    mm64(s_h + p * 65, s_w, bo, acc);

    // --- residual + LN1 ---
    float hn[64];
    float msum = 0.f;
#pragma unroll
    for (int d = 0; d < 64; d++) { hn[d] = hreg[d] + acc[d]; msum += hn[d]; }
    float mu = msum * (1.0f / 64);
    float vs = 0.f;
#pragma unroll
    for (int d = 0; d < 64; d++) { float df = hn[d] - mu; vs += df * df; }
    float rs = 1.0f / sqrtf(vs * (1.0f / 64) + EPSF);
#pragma unroll
    for (int d = 0; d < 64; d++) hn[d] = (hn[d] - mu) * rs * ln1_g[d] + ln1_b[d];

    __syncthreads();   // everyone done with s_k/s_v/s_w

    // --- FFN in two k-halves through s_k (W1t half) and s_v (W2 half) ---
#pragma unroll
    for (int d = 0; d < 64; d++) acc[d] = b2[d];
    for (int h = 0; h < 2; h++) {
        for (int i = p; i < 128 * 64; i += 128) {
            int kk = i >> 6, j = i & 63;
            s_k[i] = W1[j * 256 + h * 128 + kk];   // transposed half
        }
        for (int i = p; i < 128 * 64; i += 128) s_v[i] = W2[h * 8192 + i];
        __syncthreads();
        for (int k = 0; k < 128; k++) {
            const float4* w1c = reinterpret_cast<const float4*>(s_k + k * 64);
            float f = b1[h * 128 + k];
#pragma unroll
            for (int j4 = 0; j4 < 16; j4++) {
                float4 ww = w1c[j4];
                f += hn[j4 * 4 + 0] * ww.x + hn[j4 * 4 + 1] * ww.y
                   + hn[j4 * 4 + 2] * ww.z + hn[j4 * 4 + 3] * ww.w;
            }
            f = fmaxf(f, 0.f);
            const float4* w2r = reinterpret_cast<const float4*>(s_v + k * 64);
#pragma unroll
            for (int d4 = 0; d4 < 16; d4++) {
                float4 ww = w2r[d4];
                acc[d4 * 4 + 0] += f * ww.x;
                acc[d4 * 4 + 1] += f * ww.y;
                acc[d4 * 4 + 2] += f * ww.z;
                acc[d4 * 4 + 3] += f * ww.w;
            }
        }
        __syncthreads();
    }

    // --- residual + LN2 -> z ---
    msum = 0.f;
#pragma unroll
    for (int d = 0; d < 64; d++) { acc[d] += hn[d]; msum += acc[d]; }
    mu = msum * (1.0f / 64);
    vs = 0.f;
#pragma unroll
    for (int d = 0; d < 64; d++) { float df = acc[d] - mu; vs += df * df; }
    rs = 1.0f / sqrtf(vs * (1.0f / 64) + EPSF);
    float zr[64];
#pragma unroll
    for (int d = 0; d < 64; d++) zr[d] = (acc[d] - mu) * rs * ln2_g[d] + ln2_b[d];
    float4* zg = reinterpret_cast<float4*>(g_z + ((size_t)n * 128 + p) * 64);
#pragma unroll
    for (int d4 = 0; d4 < 16; d4++)
        zg[d4] = make_float4(zr[d4 * 4], zr[d4 * 4 + 1], zr[d4 * 4 + 2], zr[d4 * 4 + 3]);
}

// ---------------- kernel 3: quantizer (byte-identical to passing version) ----------------
#define QNT_SMEM ((Kk*Dd + Kk) * 4)

__global__ __launch_bounds__(256) void pcv_quant(const float* __restrict__ codebook,
                                                 float* __restrict__ out)
{
    extern __shared__ float sm[];
    float* s_cb = sm;
    float* s_e2 = sm + Kk * Dd;
    __shared__ float red[256];
    int tid = threadIdx.x;
    for (int i = tid; i < Kk * Dd; i += 256) s_cb[i] = codebook[i];
    __syncthreads();
    for (int k = tid; k < Kk; k += 256) {
        const float* cr = s_cb + k * 64;
        float s = 0.f;
#pragma unroll 8
        for (int j = 0; j < 64; j++) s += cr[j] * cr[j];
        s_e2[k] = s;
    }
    __syncthreads();

    int t = blockIdx.x * 256 + tid;
    const float4* zg = reinterpret_cast<const float4*>(g_z + (size_t)t * 64);
    float zr[64];
#pragma unroll
    for (int j4 = 0; j4 < 16; j4++) {
        float4 v = zg[j4];
        zr[j4 * 4] = v.x; zr[j4 * 4 + 1] = v.y; zr[j4 * 4 + 2] = v.z; zr[j4 * 4 + 3] = v.w;
    }
    float z2 = 0.f;
#pragma unroll
    for (int j = 0; j < 64; j++) z2 += zr[j] * zr[j];

    float best = 3.4e38f;
    int bi = 0;
    for (int k = 0; k < Kk; k++) {
        const float4* cr = reinterpret_cast<const float4*>(s_cb + k * 64);
        float dot = 0.f;
#pragma unroll
        for (int j4 = 0; j4 < 16; j4++) {
            float4 cv = cr[j4];
            dot += zr[j4 * 4 + 0] * cv.x;
            dot += zr[j4 * 4 + 1] * cv.y;
            dot += zr[j4 * 4 + 2] * cv.z;
            dot += zr[j4 * 4 + 3] * cv.w;
        }
        float d = __fadd_rn(__fadd_rn(z2, s_e2[k]), -__fmul_rn(2.0f, dot));
        if (d < best) { best = d; bi = k; }
    }

    float2* zqo = reinterpret_cast<float2*>(out + OFF_ZQ + (size_t)t * 64);
    const float2* cb2 = reinterpret_cast<const float2*>(s_cb + bi * 64);
#pragma unroll
    for (int j = 0; j < 32; j++) zqo[j] = cb2[j];
    out[OFF_IDX + t] = (float)bi;
    atomicAdd(&g_counts[bi], 1);

    red[tid] = best;
    __syncthreads();
    for (int s = 128; s > 0; s >>= 1) {
        if (tid < s) red[tid] += red[tid + s];
        __syncthreads();
    }
    if (tid == 0) g_sq_partial[blockIdx.x] = red[0];
}

// ---------------- kernel 4a: decode the 512 codewords once ----------------
#define DEC_SMEM ((256*64 + 256*16 + 64*16) * 4)

__global__ __launch_bounds__(256) void pcv_deccb(
    const float* __restrict__ codebook,
    const float* __restrict__ dW1, const float* __restrict__ db1,
    const float* __restrict__ dW2, const float* __restrict__ db2,
    const float* __restrict__ dWr, const float* __restrict__ dbr,
    const float* __restrict__ lng, const float* __restrict__ lnb)
{
    extern __shared__ float sm[];
    float* s_w1t = sm;               // [256][64] transposed
    float* s_w2  = sm + 256 * 64;    // [256][16]
    float* s_wr  = s_w2 + 256 * 16;  // [64][16]
    int tid = threadIdx.x;
    for (int i = tid; i < 64 * 256; i += 256) {
        int j = i >> 8, k = i & 255;
        s_w1t[k * 64 + j] = dW1[i];
    }
    for (int i = tid; i < 256 * 16; i += 256) s_w2[i] = dW2[i];
    for (int i = tid; i < 64 * 16; i += 256)  s_wr[i] = dWr[i];
    __syncthreads();

    int cw = blockIdx.x * 256 + tid;   // 0..511

    float zq[64];
    const float2* cb2 = reinterpret_cast<const float2*>(codebook + (size_t)cw * 64);
#pragma unroll
    for (int j = 0; j < 32; j++) { float2 v = cb2[j]; zq[2 * j] = v.x; zq[2 * j + 1] = v.y; }

    float y[16];
#pragma unroll
    for (int i = 0; i < 16; i++) y[i] = db2[i];
    for (int k = 0; k < 256; k++) {
        const float4* w1c = reinterpret_cast<const float4*>(s_w1t + k * 64);
        float f = db1[k];
#pragma unroll
        for (int j4 = 0; j4 < 16; j4++) {
            float4 w = w1c[j4];
            f += zq[j4 * 4 + 0] * w.x + zq[j4 * 4 + 1] * w.y
               + zq[j4 * 4 + 2] * w.z + zq[j4 * 4 + 3] * w.w;
        }
        f = fmaxf(f, 0.f);
        const float4* w2r = reinterpret_cast<const float4*>(s_w2 + k * 16);
#pragma unroll
        for (int i4 = 0; i4 < 4; i4++) {
            float4 w = w2r[i4];
            y[i4 * 4 + 0] += f * w.x;
            y[i4 * 4 + 1] += f * w.y;
            y[i4 * 4 + 2] += f * w.z;
            y[i4 * 4 + 3] += f * w.w;
        }
    }
#pragma unroll
    for (int i = 0; i < 16; i++) y[i] += dbr[i];
#pragma unroll 8
    for (int j = 0; j < 64; j++) {
        float zj = zq[j];
        const float4* wr4 = reinterpret_cast<const float4*>(s_wr + j * 16);
#pragma unroll
        for (int i4 = 0; i4 < 4; i4++) {
            float4 w = wr4[i4];
            y[i4 * 4 + 0] += zj * w.x;
            y[i4 * 4 + 1] += zj * w.y;
            y[i4 * 4 + 2] += zj * w.z;
            y[i4 * 4 + 3] += zj * w.w;
        }
    }
    // LN over PL=16
    float mu = 0.f;
#pragma unroll
    for (int i = 0; i < 16; i++) mu += y[i];
    mu *= (1.0f / 16);
    float var = 0.f;
#pragma unroll
    for (int i = 0; i < 16; i++) { float d = y[i] - mu; var += d * d; }
    var *= (1.0f / 16);
    float rs = 1.0f / sqrtf(var + EPSF);
#pragma unroll
    for (int i = 0; i < 16; i++)
        g_rec[cw * 16 + i] = (y[i] - mu) * rs * lng[i] + lnb[i];
}

// ---------------- kernel 4b: gather + denorm + rec-loss (memory-bound) ----------------
__global__ __launch_bounds__(256) void pcv_apply(
    const float* __restrict__ x,
    const float* __restrict__ revin_w, const float* __restrict__ revin_b,
    float* __restrict__ out)
{
    __shared__ float s_rec[Kk * PLn];   // 32 KB
    __shared__ float red[256];
    int tid = threadIdx.x;
    for (int i = tid; i < Kk * PLn; i += 256) s_rec[i] = g_rec[i];
    __syncthreads();

    int c = tid & 31;
    int rgrp = tid >> 5;           // 8 row groups
    float rwc = revin_w[c] + 1e-10f;   // EPS*EPS
    float rbc = revin_b[c];
    float local = 0.f;
#pragma unroll 4
    for (int it = 0; it < 16; it++) {
        int row = blockIdx.x * 128 + it * 8 + rgrp;   // (b,l) row, 0..65535
        int b = row >> 11;
        int l = row & 2047;
        int pp = l >> 4, i = l & 15;
        int n = b * 32 + c;
        int idx = (int)out[OFF_IDX + (size_t)n * 128 + pp];
        float rec = s_rec[idx * 16 + i];
        float rv = (rec - rbc) / rwc * g_std[n] + g_mean[n];
        size_t off = (size_t)row * 32 + c;
        out[OFF_R + off] = rv;
        float dx = x[off] - rv;
        local += dx * dx;
    }
    red[tid] = local;
    __syncthreads();
    for (int s = 128; s > 0; s >>= 1) {
        if (tid < s) red[tid] += red[tid + s];
        __syncthreads();
    }
    if (tid == 0) g_rec_partial[blockIdx.x] = red[0];
}

// ---------------- kernel 5: finalize scalars ----------------
__global__ void pcv_final(float* __restrict__ out)
{
    if (threadIdx.x == 0 && blockIdx.x == 0) {
        float sq = 0.f;
        for (int i = 0; i < 512; i++) sq += g_sq_partial[i];
        float recs = 0.f;
        for (int i = 0; i < 512; i++) recs += g_rec_partial[i];
        float mse = sq * (1.0f / 8388608.0f);
        float cluster = mse + 0.25f * mse;
        float rec_loss = recs * (1.0f / 2097152.0f);
        out[0] = rec_loss + 0.2f * cluster;
        out[1] = rec_loss;
        float tot = 0.f;
        for (int k = 0; k < Kk; k++) tot += (float)g_counts[k];
        float inv = 1.0f / (tot + EPSF);
        float ent = 0.f;
        for (int k = 0; k < Kk; k++) {
            float pr = (float)g_counts[k] * inv;
            ent += pr * logf(pr + EPSF);
        }
        out[OFF_PERP] = expf(-ent);
    }
}

// ---------------- launch ----------------
extern "C" void kernel_launch(void* const* d_in, const int* in_sizes, int n_in,
                              void* d_out, int out_size)
{
    const float* x       = (const float*)d_in[0];
    const float* revin_w = (const float*)d_in[1];
    const float* revin_b = (const float*)d_in[2];
    const float* inp_W   = (const float*)d_in[3];
    const float* inp_b   = (const float*)d_in[4];
    const float* Wq = (const float*)d_in[5];  const float* bq = (const float*)d_in[6];
    const float* Wk = (const float*)d_in[7];  const float* bk = (const float*)d_in[8];
    const float* Wv = (const float*)d_in[9];  const float* bv = (const float*)d_in[10];
    const float* Wo = (const float*)d_in[11]; const float* bo = (const float*)d_in[12];
    const float* ln1_g = (const float*)d_in[13]; const float* ln1_b = (const float*)d_in[14];
    const float* W1 = (const float*)d_in[15]; const float* b1 = (const float*)d_in[16];
    const float* W2 = (const float*)d_in[17]; const float* b2 = (const float*)d_in[18];
    const float* ln2_g = (const float*)d_in[19]; const float* ln2_b = (const float*)d_in[20];
    const float* codebook = (const float*)d_in[21];
    const float* dW1 = (const float*)d_in[22]; const float* db1 = (const float*)d_in[23];
    const float* dW2 = (const float*)d_in[24]; const float* db2 = (const float*)d_in[25];
    const float* dWr = (const float*)d_in[26]; const float* dbr = (const float*)d_in[27];
    const float* dlg = (const float*)d_in[28]; const float* dlb = (const float*)d_in[29];
    float* out = (float*)d_out;

    cudaFuncSetAttribute(pcv_encoder, cudaFuncAttributeMaxDynamicSharedMemorySize, ENC_SMEM);
    cudaFuncSetAttribute(pcv_quant,   cudaFuncAttributeMaxDynamicSharedMemorySize, QNT_SMEM);
    cudaFuncSetAttribute(pcv_deccb,   cudaFuncAttributeMaxDynamicSharedMemorySize, DEC_SMEM);

    pcv_revin<<<Bn, 256>>>(x);
    pcv_deccb<<<2, 256, DEC_SMEM>>>(codebook, dW1, db1, dW2, db2, dWr, dbr, dlg, dlb);
    pcv_encoder<<<NSEQ, 128, ENC_SMEM>>>(x, revin_w, revin_b, inp_W, inp_b,
                                         Wq, bq, Wk, bk, Wv, bv, Wo, bo,
                                         ln1_g, ln1_b, W1, b1, W2, b2, ln2_g, ln2_b);
    pcv_quant<<<NTOK / 256, 256, QNT_SMEM>>>(codebook, out);
    pcv_apply<<<512, 256>>>(x, revin_w, revin_b, out);
    pcv_final<<<1, 32>>>(out);
}

// round 6
// speedup vs baseline: 1.2814x; 1.0458x over previous
#include <cuda_runtime.h>
#include <math.h>
#include <stdint.h>

// ---------------- problem constants ----------------
#define Bn   32
#define Ln   2048
#define Cn   32
#define PLn  16
#define Pp   128
#define Dd   64
#define Hh   256
#define Kk   512
#define NSEQ (Bn*Cn)        // 1024
#define NTOK (NSEQ*Pp)      // 131072
#define EPSF 1e-5f

// output layout (flattened reference return tuple, float32)
#define OFF_ZQ   ((size_t)2)
#define OFF_R    (OFF_ZQ + (size_t)NTOK*Dd)            // 8388610
#define OFF_IDX  (OFF_R + (size_t)Bn*Ln*Cn)            // 10485762
#define OFF_PERP (OFF_IDX + (size_t)NTOK)              // 10616834

// ---------------- device scratch ----------------
__device__ float g_mean[NSEQ];
__device__ float g_std[NSEQ];
__device__ float g_h[(size_t)NTOK*Dd];      // h (pre-attention), 33.5 MB
__device__ float g_q[(size_t)NTOK*Dd];      // q, later reused as hn (post-LN1)
__device__ float g_k[(size_t)NTOK*Dd];
__device__ float g_v[(size_t)NTOK*Dd];
__device__ float g_z[(size_t)NTOK*Dd];      // encoder output z
__device__ int   g_counts[Kk];
__device__ float g_sq_partial[512];
__device__ float g_rec_partial[512];
__device__ float g_rec[Kk*PLn];             // per-codeword decoded patch (post-LN)

// ---------------- kernel 1: RevIN stats + zero counts ----------------
__global__ __launch_bounds__(256) void pcv_revin(const float* __restrict__ x)
{
    int b = blockIdx.x;
    int t = threadIdx.x;
    int c = t & 31;
    int g = t >> 5;
    if (b == 0) {
        for (int i = t; i < Kk; i += 256) g_counts[i] = 0;
    }
    float s = 0.f, s2 = 0.f;
    const float* xb = x + (size_t)b * Ln * Cn + c;
    for (int l = g; l < Ln; l += 8) {
        float v = xb[(size_t)l * Cn];
        s += v; s2 += v * v;
    }
    __shared__ float sh_s[256], sh_q[256];
    sh_s[t] = s; sh_q[t] = s2;
    __syncthreads();
    if (g == 0) {
        float ss = 0.f, qq = 0.f;
#pragma unroll
        for (int i = 0; i < 8; i++) { ss += sh_s[i * 32 + c]; qq += sh_q[i * 32 + c]; }
        float mean = ss * (1.0f / Ln);
        float var  = qq * (1.0f / Ln) - mean * mean;
        g_mean[b * 32 + c] = mean;
        g_std [b * 32 + c] = sqrtf(var + EPSF);
    }
}

// 64x64 row-matmul: acc[d] = bias[d] + sum_k hrow[k]*w[k*64+d]   (unchanged math)
__device__ __forceinline__ void mm64(const float* __restrict__ hrow,
                                     const float* __restrict__ w,
                                     const float* __restrict__ bias,
                                     float* acc)
{
#pragma unroll
    for (int d = 0; d < 64; d++) acc[d] = bias[d];
#pragma unroll 4
    for (int k = 0; k < 64; k++) {
        float hk = hrow[k];
        const float4* w4 = reinterpret_cast<const float4*>(w + k * 64);
#pragma unroll
        for (int d4 = 0; d4 < 16; d4++) {
            float4 ww = w4[d4];
            acc[d4 * 4 + 0] += hk * ww.x;
            acc[d4 * 4 + 1] += hk * ww.y;
            acc[d4 * 4 + 2] += hk * ww.z;
            acc[d4 * 4 + 3] += hk * ww.w;
        }
    }
}

__device__ __forceinline__ void store_row64(float* dst, const float* v)
{
    float4* d4 = reinterpret_cast<float4*>(dst);
#pragma unroll
    for (int j = 0; j < 16; j++)
        d4[j] = make_float4(v[4*j], v[4*j+1], v[4*j+2], v[4*j+3]);
}

__device__ __forceinline__ void load_row64(float* v, const float* src)
{
    const float4* s4 = reinterpret_cast<const float4*>(src);
#pragma unroll
    for (int j = 0; j < 16; j++) {
        float4 t = s4[j];
        v[4*j] = t.x; v[4*j+1] = t.y; v[4*j+2] = t.z; v[4*j+3] = t.w;
    }
}

// ---------------- kernel 2: embed + Q/K/V (streaming, 16 warps/SM) ----------------
#define QKV_SMEM ((256*65 + 64*64) * 4)

__global__ void __launch_bounds__(256, 2) pcv_qkvh(
    const float* __restrict__ x,
    const float* __restrict__ revin_w, const float* __restrict__ revin_b,
    const float* __restrict__ inp_W,   const float* __restrict__ inp_b,
    const float* __restrict__ Wq, const float* __restrict__ bq,
    const float* __restrict__ Wk, const float* __restrict__ bk,
    const float* __restrict__ Wv, const float* __restrict__ bv)
{
    extern __shared__ float sm[];
    float* s_h = sm;               // 256*65 private rows
    float* s_w = sm + 256 * 65;    // 4096 weight staging

    int tid = threadIdx.x;
    int t0  = blockIdx.x * 256 + tid;
    int n = t0 >> 7, p = t0 & 127;
    int b = n >> 5, c = n & 31;

    float mean = g_mean[n];
    float istd = 1.0f / g_std[n];
    float rw = revin_w[c], rb = revin_b[c];
    float* hrow = s_h + tid * 65;

    // inp_W
    for (int i = tid; i < 16 * 64; i += 256) s_w[i] = inp_W[i];
    __syncthreads();

    float acc[64];
#pragma unroll
    for (int d = 0; d < 64; d++) acc[d] = inp_b[d];
    const float* xp = x + ((size_t)b * Ln + (size_t)p * PLn) * Cn + c;
#pragma unroll
    for (int j = 0; j < 16; j++) {
        float xv = (xp[(size_t)j * Cn] - mean) * istd * rw + rb;
        const float4* w4 = reinterpret_cast<const float4*>(s_w + j * 64);
#pragma unroll
        for (int d4 = 0; d4 < 16; d4++) {
            float4 ww = w4[d4];
            acc[d4 * 4 + 0] += xv * ww.x;
            acc[d4 * 4 + 1] += xv * ww.y;
            acc[d4 * 4 + 2] += xv * ww.z;
            acc[d4 * 4 + 3] += xv * ww.w;
        }
    }
#pragma unroll
    for (int d = 0; d < 64; d++) hrow[d] = acc[d];
    store_row64(g_h + (size_t)t0 * 64, acc);
    __syncthreads();

    // Q
    for (int i = tid; i < 4096; i += 256) s_w[i] = Wq[i];
    __syncthreads();
    mm64(hrow, s_w, bq, acc);
    store_row64(g_q + (size_t)t0 * 64, acc);
    __syncthreads();
    // K
    for (int i = tid; i < 4096; i += 256) s_w[i] = Wk[i];
    __syncthreads();
    mm64(hrow, s_w, bk, acc);
    store_row64(g_k + (size_t)t0 * 64, acc);
    __syncthreads();
    // V
    for (int i = tid; i < 4096; i += 256) s_w[i] = Wv[i];
    __syncthreads();
    mm64(hrow, s_w, bv, acc);
    store_row64(g_v + (size_t)t0 * 64, acc);
}

// ---------------- kernel 3: attention + Wo + LN1 (per-sequence blocks) ----------------
#define SKV 68   // smem row stride for k/v (float4-aligned, low write conflict)
#define ATT_SMEM ((128*SKV*2 + 64*64) * 4)

__global__ void __launch_bounds__(128, 2) pcv_attn(
    const float* __restrict__ Wo, const float* __restrict__ bo,
    const float* __restrict__ ln1_g, const float* __restrict__ ln1_b)
{
    extern __shared__ float sm[];
    float* s_k = sm;
    float* s_v = sm + 128 * SKV;
    float* s_w = s_v + 128 * SKV;

    int n = blockIdx.x;
    int p = threadIdx.x;
    int t0 = n * 128 + p;

    // coalesced load of K,V tiles into smem
    const float4* gk = reinterpret_cast<const float4*>(g_k + (size_t)n * 128 * 64);
    const float4* gv = reinterpret_cast<const float4*>(g_v + (size_t)n * 128 * 64);
    for (int e = p; e < 2048; e += 128) {
        int row = e >> 4, c4 = e & 15;
        *reinterpret_cast<float4*>(s_k + row * SKV + c4 * 4) = gk[e];
        *reinterpret_cast<float4*>(s_v + row * SKV + c4 * 4) = gv[e];
    }
    for (int i = p; i < 4096; i += 128) s_w[i] = Wo[i];

    // q row into registers
    float qreg[64];
    load_row64(qreg, g_q + (size_t)t0 * 64);
    __syncthreads();

    // --- attention (identical math) ---
    float arow[64];
#pragma unroll
    for (int hh = 0; hh < 4; hh++) {
        float qh[16];
#pragma unroll
        for (int j = 0; j < 16; j++) qh[j] = qreg[hh * 16 + j];
        float m = -1e30f, lsum = 0.f;
        float oac[16];
#pragma unroll
        for (int j = 0; j < 16; j++) oac[j] = 0.f;
#pragma unroll 2
        for (int pk = 0; pk < 128; pk++) {
            const float4* kr = reinterpret_cast<const float4*>(s_k + pk * SKV + hh * 16);
            float s = 0.f;
#pragma unroll
            for (int j4 = 0; j4 < 4; j4++) {
                float4 kv = kr[j4];
                s += qh[j4 * 4 + 0] * kv.x + qh[j4 * 4 + 1] * kv.y
                   + qh[j4 * 4 + 2] * kv.z + qh[j4 * 4 + 3] * kv.w;
            }
            s *= 0.25f;
            float mn   = fmaxf(m, s);
            float corr = __expf(m - mn);
            float w    = __expf(s - mn);
            lsum = lsum * corr + w;
            const float4* vr = reinterpret_cast<const float4*>(s_v + pk * SKV + hh * 16);
#pragma unroll
            for (int j4 = 0; j4 < 4; j4++) {
                float4 vv = vr[j4];
                oac[j4 * 4 + 0] = oac[j4 * 4 + 0] * corr + w * vv.x;
                oac[j4 * 4 + 1] = oac[j4 * 4 + 1] * corr + w * vv.y;
                oac[j4 * 4 + 2] = oac[j4 * 4 + 2] * corr + w * vv.z;
                oac[j4 * 4 + 3] = oac[j4 * 4 + 3] * corr + w * vv.w;
            }
            m = mn;
        }
        float inv = 1.0f / lsum;
#pragma unroll
        for (int j = 0; j < 16; j++) arow[hh * 16 + j] = oac[j] * inv;
    }
    __syncthreads();   // all done reading s_k/s_v

    // stage arow in (now free) s_k row, project with Wo
    store_row64(s_k + p * SKV, arow);
    float acc[64];
    mm64(s_k + p * SKV, s_w, bo, acc);

    // residual + LN1
    float hreg[64];
    load_row64(hreg, g_h + (size_t)t0 * 64);
    float hn[64];
    float msum = 0.f;
#pragma unroll
    for (int d = 0; d < 64; d++) { hn[d] = hreg[d] + acc[d]; msum += hn[d]; }
    float mu = msum * (1.0f / 64);
    float vs = 0.f;
#pragma unroll
    for (int d = 0; d < 64; d++) { float df = hn[d] - mu; vs += df * df; }
    float rs = 1.0f / sqrtf(vs * (1.0f / 64) + EPSF);
#pragma unroll
    for (int d = 0; d < 64; d++) hn[d] = (hn[d] - mu) * rs * ln1_g[d] + ln1_b[d];

    store_row64(g_q + (size_t)t0 * 64, hn);   // reuse g_q as hn storage
}

// ---------------- kernel 4: FFN + residual + LN2 (streaming) ----------------
#define FFN_SMEM ((128*64*2) * 4)

__global__ void __launch_bounds__(128, 3) pcv_ffn(
    const float* __restrict__ W1, const float* __restrict__ b1,
    const float* __restrict__ W2, const float* __restrict__ b2,
    const float* __restrict__ ln2_g, const float* __restrict__ ln2_b)
{
    extern __shared__ float sm[];
    float* s_w1t = sm;              // [128][64] transposed half
    float* s_w2  = sm + 128 * 64;   // [128][64] half

    int tid = threadIdx.x;
    int t = blockIdx.x * 128 + tid;

    float hn[64];
    load_row64(hn, g_q + (size_t)t * 64);

    float acc[64];
#pragma unroll
    for (int d = 0; d < 64; d++) acc[d] = b2[d];

    for (int h = 0; h < 2; h++) {
        if (h) __syncthreads();
        for (int i = tid; i < 128 * 64; i += 128) {
            int kk = i >> 6, j = i & 63;
            s_w1t[i] = W1[j * 256 + h * 128 + kk];
        }
        for (int i = tid; i < 128 * 64; i += 128) s_w2[i] = W2[h * 8192 + i];
        __syncthreads();
        for (int k = 0; k < 128; k++) {
            const float4* w1c = reinterpret_cast<const float4*>(s_w1t + k * 64);
            float f = b1[h * 128 + k];
#pragma unroll
            for (int j4 = 0; j4 < 16; j4++) {
                float4 ww = w1c[j4];
                f += hn[j4 * 4 + 0] * ww.x + hn[j4 * 4 + 1] * ww.y
                   + hn[j4 * 4 + 2] * ww.z + hn[j4 * 4 + 3] * ww.w;
            }
            f = fmaxf(f, 0.f);
            const float4* w2r = reinterpret_cast<const float4*>(s_w2 + k * 64);
#pragma unroll
            for (int d4 = 0; d4 < 16; d4++) {
                float4 ww = w2r[d4];
                acc[d4 * 4 + 0] += f * ww.x;
                acc[d4 * 4 + 1] += f * ww.y;
                acc[d4 * 4 + 2] += f * ww.z;
                acc[d4 * 4 + 3] += f * ww.w;
            }
        }
    }

    // residual + LN2 -> z
    float msum = 0.f;
#pragma unroll
    for (int d = 0; d < 64; d++) { acc[d] += hn[d]; msum += acc[d]; }
    float mu = msum * (1.0f / 64);
    float vs = 0.f;
#pragma unroll
    for (int d = 0; d < 64; d++) { float df = acc[d] - mu; vs += df * df; }
    float rs = 1.0f / sqrtf(vs * (1.0f / 64) + EPSF);
    float zr[64];
#pragma unroll
    for (int d = 0; d < 64; d++) zr[d] = (acc[d] - mu) * rs * ln2_g[d] + ln2_b[d];
    store_row64(g_z + (size_t)t * 64, zr);
}

// ---------------- kernel 5: quantizer v2 (2 tokens/thread, chunked codebook) ----------------
#define QNT_SMEM2 ((128*64 + 128) * 4)

__global__ void __launch_bounds__(128, 3) pcv_quant(const float* __restrict__ codebook,
                                                    float* __restrict__ out)
{
    extern __shared__ float sm[];
    float* s_cb = sm;            // 128 rows chunk
    float* s_e2 = sm + 128 * 64;
    __shared__ float red[128];
    int tid = threadIdx.x;
    int tA = blockIdx.x * 256 + tid;
    int tB = tA + 128;

    float zA[64], zB[64];
    load_row64(zA, g_z + (size_t)tA * 64);
    load_row64(zB, g_z + (size_t)tB * 64);
    float z2A = 0.f, z2B = 0.f;
#pragma unroll
    for (int j = 0; j < 64; j++) z2A += zA[j] * zA[j];
#pragma unroll
    for (int j = 0; j < 64; j++) z2B += zB[j] * zB[j];

    float bestA = 3.4e38f, bestB = 3.4e38f;
    int biA = 0, biB = 0;

    for (int cch = 0; cch < 4; cch++) {
        if (cch) __syncthreads();
        for (int i = tid; i < 128 * 64; i += 128) s_cb[i] = codebook[cch * 8192 + i];
        __syncthreads();
        {   // e2 for this chunk (one row per thread), same serial j order as before
            const float* cr = s_cb + tid * 64;
            float s = 0.f;
#pragma unroll 8
            for (int j = 0; j < 64; j++) s += cr[j] * cr[j];
            s_e2[tid] = s;
        }
        __syncthreads();
        for (int kk = 0; kk < 128; kk++) {
            const float4* cr = reinterpret_cast<const float4*>(s_cb + kk * 64);
            float dotA = 0.f, dotB = 0.f;
#pragma unroll
            for (int j4 = 0; j4 < 16; j4++) {
                float4 cv = cr[j4];
                dotA += zA[j4 * 4 + 0] * cv.x;
                dotA += zA[j4 * 4 + 1] * cv.y;
                dotA += zA[j4 * 4 + 2] * cv.z;
                dotA += zA[j4 * 4 + 3] * cv.w;
                dotB += zB[j4 * 4 + 0] * cv.x;
                dotB += zB[j4 * 4 + 1] * cv.y;
                dotB += zB[j4 * 4 + 2] * cv.z;
                dotB += zB[j4 * 4 + 3] * cv.w;
            }
            float e2k = s_e2[kk];
            float dA = __fadd_rn(__fadd_rn(z2A, e2k), -__fmul_rn(2.0f, dotA));
            float dB = __fadd_rn(__fadd_rn(z2B, e2k), -__fmul_rn(2.0f, dotB));
            int kg = cch * 128 + kk;
            if (dA < bestA) { bestA = dA; biA = kg; }
            if (dB < bestB) { bestB = dB; biB = kg; }
        }
    }

    // write z_q (gather from global codebook) + indices
    {
        float2* zqo = reinterpret_cast<float2*>(out + OFF_ZQ + (size_t)tA * 64);
        const float2* cb2 = reinterpret_cast<const float2*>(codebook + (size_t)biA * 64);
#pragma unroll
        for (int j = 0; j < 32; j++) zqo[j] = cb2[j];
    }
    {
        float2* zqo = reinterpret_cast<float2*>(out + OFF_ZQ + (size_t)tB * 64);
        const float2* cb2 = reinterpret_cast<const float2*>(codebook + (size_t)biB * 64);
#pragma unroll
        for (int j = 0; j < 32; j++) zqo[j] = cb2[j];
    }
    out[OFF_IDX + tA] = (float)biA;
    out[OFF_IDX + tB] = (float)biB;
    atomicAdd(&g_counts[biA], 1);
    atomicAdd(&g_counts[biB], 1);

    red[tid] = bestA + bestB;
    __syncthreads();
    for (int s = 64; s > 0; s >>= 1) {
        if (tid < s) red[tid] += red[tid + s];
        __syncthreads();
    }
    if (tid == 0) g_sq_partial[blockIdx.x] = red[0];
}

// ---------------- kernel 6: decode the 512 codewords once ----------------
#define DEC_SMEM ((256*64 + 256*16 + 64*16) * 4)

__global__ __launch_bounds__(256) void pcv_deccb(
    const float* __restrict__ codebook,
    const float* __restrict__ dW1, const float* __restrict__ db1,
    const float* __restrict__ dW2, const float* __restrict__ db2,
    const float* __restrict__ dWr, const float* __restrict__ dbr,
    const float* __restrict__ lng, const float* __restrict__ lnb)
{
    extern __shared__ float sm[];
    float* s_w1t = sm;
    float* s_w2  = sm + 256 * 64;
    float* s_wr  = s_w2 + 256 * 16;
    int tid = threadIdx.x;
    for (int i = tid; i < 64 * 256; i += 256) {
        int j = i >> 8, k = i & 255;
        s_w1t[k * 64 + j] = dW1[i];
    }
    for (int i = tid; i < 256 * 16; i += 256) s_w2[i] = dW2[i];
    for (int i = tid; i < 64 * 16; i += 256)  s_wr[i] = dWr[i];
    __syncthreads();

    int cw = blockIdx.x * 256 + tid;

    float zq[64];
    const float2* cb2 = reinterpret_cast<const float2*>(codebook + (size_t)cw * 64);
#pragma unroll
    for (int j = 0; j < 32; j++) { float2 v = cb2[j]; zq[2 * j] = v.x; zq[2 * j + 1] = v.y; }

    float y[16];
#pragma unroll
    for (int i = 0; i < 16; i++) y[i] = db2[i];
    for (int k = 0; k < 256; k++) {
        const float4* w1c = reinterpret_cast<const float4*>(s_w1t + k * 64);
        float f = db1[k];
#pragma unroll
        for (int j4 = 0; j4 < 16; j4++) {
            float4 w = w1c[j4];
            f += zq[j4 * 4 + 0] * w.x + zq[j4 * 4 + 1] * w.y
               + zq[j4 * 4 + 2] * w.z + zq[j4 * 4 + 3] * w.w;
        }
        f = fmaxf(f, 0.f);
        const float4* w2r = reinterpret_cast<const float4*>(s_w2 + k * 16);
#pragma unroll
        for (int i4 = 0; i4 < 4; i4++) {
            float4 w = w2r[i4];
            y[i4 * 4 + 0] += f * w.x;
            y[i4 * 4 + 1] += f * w.y;
            y[i4 * 4 + 2] += f * w.z;
            y[i4 * 4 + 3] += f * w.w;
        }
    }
#pragma unroll
    for (int i = 0; i < 16; i++) y[i] += dbr[i];
#pragma unroll 8
    for (int j = 0; j < 64; j++) {
        float zj = zq[j];
        const float4* wr4 = reinterpret_cast<const float4*>(s_wr + j * 16);
#pragma unroll
        for (int i4 = 0; i4 < 4; i4++) {
            float4 w = wr4[i4];
            y[i4 * 4 + 0] += zj * w.x;
            y[i4 * 4 + 1] += zj * w.y;
            y[i4 * 4 + 2] += zj * w.z;
            y[i4 * 4 + 3] += zj * w.w;
        }
    }
    float mu = 0.f;
#pragma unroll
    for (int i = 0; i < 16; i++) mu += y[i];
    mu *= (1.0f / 16);
    float var = 0.f;
#pragma unroll
    for (int i = 0; i < 16; i++) { float d = y[i] - mu; var += d * d; }
    var *= (1.0f / 16);
    float rs = 1.0f / sqrtf(var + EPSF);
#pragma unroll
    for (int i = 0; i < 16; i++)
        g_rec[cw * 16 + i] = (y[i] - mu) * rs * lng[i] + lnb[i];
}

// ---------------- kernel 7: gather + denorm + rec-loss ----------------
__global__ __launch_bounds__(256) void pcv_apply(
    const float* __restrict__ x,
    const float* __restrict__ revin_w, const float* __restrict__ revin_b,
    float* __restrict__ out)
{
    __shared__ float s_rec[Kk * PLn];
    __shared__ float red[256];
    int tid = threadIdx.x;
    for (int i = tid; i < Kk * PLn; i += 256) s_rec[i] = g_rec[i];
    __syncthreads();

    int c = tid & 31;
    int rgrp = tid >> 5;
    float rwc = revin_w[c] + 1e-10f;
    float rbc = revin_b[c];
    float local = 0.f;
#pragma unroll 4
    for (int it = 0; it < 16; it++) {
        int row = blockIdx.x * 128 + it * 8 + rgrp;
        int b = row >> 11;
        int l = row & 2047;
        int pp = l >> 4, i = l & 15;
        int n = b * 32 + c;
        int idx = (int)out[OFF_IDX + (size_t)n * 128 + pp];
        float rec = s_rec[idx * 16 + i];
        float rv = (rec - rbc) / rwc * g_std[n] + g_mean[n];
        size_t off = (size_t)row * 32 + c;
        out[OFF_R + off] = rv;
        float dx = x[off] - rv;
        local += dx * dx;
    }
    red[tid] = local;
    __syncthreads();
    for (int s = 128; s > 0; s >>= 1) {
        if (tid < s) red[tid] += red[tid + s];
        __syncthreads();
    }
    if (tid == 0) g_rec_partial[blockIdx.x] = red[0];
}

// ---------------- kernel 8: finalize scalars ----------------
__global__ void pcv_final(float* __restrict__ out)
{
    if (threadIdx.x == 0 && blockIdx.x == 0) {
        float sq = 0.f;
        for (int i = 0; i < 512; i++) sq += g_sq_partial[i];
        float recs = 0.f;
        for (int i = 0; i < 512; i++) recs += g_rec_partial[i];
        float mse = sq * (1.0f / 8388608.0f);
        float cluster = mse + 0.25f * mse;
        float rec_loss = recs * (1.0f / 2097152.0f);
        out[0] = rec_loss + 0.2f * cluster;
        out[1] = rec_loss;
        float tot = 0.f;
        for (int k = 0; k < Kk; k++) tot += (float)g_counts[k];
        float inv = 1.0f / (tot + EPSF);
        float ent = 0.f;
        for (int k = 0; k < Kk; k++) {
            float pr = (float)g_counts[k] * inv;
            ent += pr * logf(pr + EPSF);
        }
        out[OFF_PERP] = expf(-ent);
    }
}

// ---------------- launch ----------------
extern "C" void kernel_launch(void* const* d_in, const int* in_sizes, int n_in,
                              void* d_out, int out_size)
{
    const float* x       = (const float*)d_in[0];
    const float* revin_w = (const float*)d_in[1];
    const float* revin_b = (const float*)d_in[2];
    const float* inp_W   = (const float*)d_in[3];
    const float* inp_b   = (const float*)d_in[4];
    const float* Wq = (const float*)d_in[5];  const float* bq = (const float*)d_in[6];
    const float* Wk = (const float*)d_in[7];  const float* bk = (const float*)d_in[8];
    const float* Wv = (const float*)d_in[9];  const float* bv = (const float*)d_in[10];
    const float* Wo = (const float*)d_in[11]; const float* bo = (const float*)d_in[12];
    const float* ln1_g = (const float*)d_in[13]; const float* ln1_b = (const float*)d_in[14];
    const float* W1 = (const float*)d_in[15]; const float* b1 = (const float*)d_in[16];
    const float* W2 = (const float*)d_in[17]; const float* b2 = (const float*)d_in[18];
    const float* ln2_g = (const float*)d_in[19]; const float* ln2_b = (const float*)d_in[20];
    const float* codebook = (const float*)d_in[21];
    const float* dW1 = (const float*)d_in[22]; const float* db1 = (const float*)d_in[23];
    const float* dW2 = (const float*)d_in[24]; const float* db2 = (const float*)d_in[25];
    const float* dWr = (const float*)d_in[26]; const float* dbr = (const float*)d_in[27];
    const float* dlg = (const float*)d_in[28]; const float* dlb = (const float*)d_in[29];
    float* out = (float*)d_out;

    cudaFuncSetAttribute(pcv_qkvh,  cudaFuncAttributeMaxDynamicSharedMemorySize, QKV_SMEM);
    cudaFuncSetAttribute(pcv_attn,  cudaFuncAttributeMaxDynamicSharedMemorySize, ATT_SMEM);
    cudaFuncSetAttribute(pcv_ffn,   cudaFuncAttributeMaxDynamicSharedMemorySize, FFN_SMEM);
    cudaFuncSetAttribute(pcv_quant, cudaFuncAttributeMaxDynamicSharedMemorySize, QNT_SMEM2);
    cudaFuncSetAttribute(pcv_deccb, cudaFuncAttributeMaxDynamicSharedMemorySize, DEC_SMEM);

    pcv_revin<<<Bn, 256>>>(x);
    pcv_deccb<<<2, 256, DEC_SMEM>>>(codebook, dW1, db1, dW2, db2, dWr, dbr, dlg, dlb);
    pcv_qkvh<<<NTOK / 256, 256, QKV_SMEM>>>(x, revin_w, revin_b, inp_W, inp_b,
                                            Wq, bq, Wk, bk, Wv, bv);
    pcv_attn<<<NSEQ, 128, ATT_SMEM>>>(Wo, bo, ln1_g, ln1_b);
    pcv_ffn<<<NTOK / 128, 128, FFN_SMEM>>>(W1, b1, W2, b2, ln2_g, ln2_b);
    pcv_quant<<<NTOK / 256, 128, QNT_SMEM2>>>(codebook, out);
    pcv_apply<<<512, 256>>>(x, revin_w, revin_b, out);
    pcv_final<<<1, 32>>>(out);
}

// round 8
// speedup vs baseline: 1.2980x; 1.0130x over previous
#include <cuda_runtime.h>
#include <math.h>
#include <stdint.h>

// ---------------- problem constants ----------------
#define Bn   32
#define Ln   2048
#define Cn   32
#define PLn  16
#define Pp   128
#define Dd   64
#define Hh   256
#define Kk   512
#define NSEQ (Bn*Cn)        // 1024
#define NTOK (NSEQ*Pp)      // 131072
#define EPSF 1e-5f

// output layout (flattened reference return tuple, float32)
#define OFF_ZQ   ((size_t)2)
#define OFF_R    (OFF_ZQ + (size_t)NTOK*Dd)            // 8388610
#define OFF_IDX  (OFF_R + (size_t)Bn*Ln*Cn)            // 10485762
#define OFF_PERP (OFF_IDX + (size_t)NTOK)              // 10616834

// ---------------- device scratch ----------------
__device__ float g_mean[NSEQ];
__device__ float g_std[NSEQ];
__device__ float g_h[(size_t)NTOK*Dd];
__device__ float g_q[(size_t)NTOK*Dd];      // q, later reused as hn (post-LN1)
__device__ float g_k[(size_t)NTOK*Dd];
__device__ float g_v[(size_t)NTOK*Dd];
__device__ float g_z[(size_t)NTOK*Dd];
__device__ int   g_counts[Kk];
__device__ float g_sq_partial[512];
__device__ float g_rec_partial[512];
__device__ float g_rec[Kk*PLn];

// ---------------- kernel 1: RevIN stats + zero counts ----------------
__global__ __launch_bounds__(256) void pcv_revin(const float* __restrict__ x)
{
    int b = blockIdx.x;
    int t = threadIdx.x;
    int c = t & 31;
    int g = t >> 5;
    if (b == 0) {
        for (int i = t; i < Kk; i += 256) g_counts[i] = 0;
    }
    float s = 0.f, s2 = 0.f;
    const float* xb = x + (size_t)b * Ln * Cn + c;
    for (int l = g; l < Ln; l += 8) {
        float v = xb[(size_t)l * Cn];
        s += v; s2 += v * v;
    }
    __shared__ float sh_s[256], sh_q[256];
    sh_s[t] = s; sh_q[t] = s2;
    __syncthreads();
    if (g == 0) {
        float ss = 0.f, qq = 0.f;
#pragma unroll
        for (int i = 0; i < 8; i++) { ss += sh_s[i * 32 + c]; qq += sh_q[i * 32 + c]; }
        float mean = ss * (1.0f / Ln);
        float var  = qq * (1.0f / Ln) - mean * mean;
        g_mean[b * 32 + c] = mean;
        g_std [b * 32 + c] = sqrtf(var + EPSF);
    }
}

// 64x64 row-matmul (unchanged math)
__device__ __forceinline__ void mm64(const float* __restrict__ hrow,
                                     const float* __restrict__ w,
                                     const float* __restrict__ bias,
                                     float* acc)
{
#pragma unroll
    for (int d = 0; d < 64; d++) acc[d] = bias[d];
#pragma unroll 4
    for (int k = 0; k < 64; k++) {
        float hk = hrow[k];
        const float4* w4 = reinterpret_cast<const float4*>(w + k * 64);
#pragma unroll
        for (int d4 = 0; d4 < 16; d4++) {
            float4 ww = w4[d4];
            acc[d4 * 4 + 0] += hk * ww.x;
            acc[d4 * 4 + 1] += hk * ww.y;
            acc[d4 * 4 + 2] += hk * ww.z;
            acc[d4 * 4 + 3] += hk * ww.w;
        }
    }
}

__device__ __forceinline__ void store_row64(float* dst, const float* v)
{
    float4* d4 = reinterpret_cast<float4*>(dst);
#pragma unroll
    for (int j = 0; j < 16; j++)
        d4[j] = make_float4(v[4*j], v[4*j+1], v[4*j+2], v[4*j+3]);
}

__device__ __forceinline__ void load_row64(float* v, const float* src)
{
    const float4* s4 = reinterpret_cast<const float4*>(src);
#pragma unroll
    for (int j = 0; j < 16; j++) {
        float4 t = s4[j];
        v[4*j] = t.x; v[4*j+1] = t.y; v[4*j+2] = t.z; v[4*j+3] = t.w;
    }
}

// ---------------- kernel 2: embed + Q/K/V ----------------
#define QKV_SMEM ((256*65 + 64*64) * 4)

__global__ void __launch_bounds__(256, 2) pcv_qkvh(
    const float* __restrict__ x,
    const float* __restrict__ revin_w, const float* __restrict__ revin_b,
    const float* __restrict__ inp_W,   const float* __restrict__ inp_b,
    const float* __restrict__ Wq, const float* __restrict__ bq,
    const float* __restrict__ Wk, const float* __restrict__ bk,
    const float* __restrict__ Wv, const float* __restrict__ bv)
{
    extern __shared__ float sm[];
    float* s_h = sm;
    float* s_w = sm + 256 * 65;

    int tid = threadIdx.x;
    int t0  = blockIdx.x * 256 + tid;
    int n = t0 >> 7, p = t0 & 127;
    int b = n >> 5, c = n & 31;

    float mean = g_mean[n];
    float istd = 1.0f / g_std[n];
    float rw = revin_w[c], rb = revin_b[c];
    float* hrow = s_h + tid * 65;

    for (int i = tid; i < 16 * 64; i += 256) s_w[i] = inp_W[i];
    __syncthreads();

    float acc[64];
#pragma unroll
    for (int d = 0; d < 64; d++) acc[d] = inp_b[d];
    const float* xp = x + ((size_t)b * Ln + (size_t)p * PLn) * Cn + c;
#pragma unroll
    for (int j = 0; j < 16; j++) {
        float xv = (xp[(size_t)j * Cn] - mean) * istd * rw + rb;
        const float4* w4 = reinterpret_cast<const float4*>(s_w + j * 64);
#pragma unroll
        for (int d4 = 0; d4 < 16; d4++) {
            float4 ww = w4[d4];
            acc[d4 * 4 + 0] += xv * ww.x;
            acc[d4 * 4 + 1] += xv * ww.y;
            acc[d4 * 4 + 2] += xv * ww.z;
            acc[d4 * 4 + 3] += xv * ww.w;
        }
    }
#pragma unroll
    for (int d = 0; d < 64; d++) hrow[d] = acc[d];
    store_row64(g_h + (size_t)t0 * 64, acc);
    __syncthreads();

    for (int i = tid; i < 4096; i += 256) s_w[i] = Wq[i];
    __syncthreads();
    mm64(hrow, s_w, bq, acc);
    store_row64(g_q + (size_t)t0 * 64, acc);
    __syncthreads();
    for (int i = tid; i < 4096; i += 256) s_w[i] = Wk[i];
    __syncthreads();
    mm64(hrow, s_w, bk, acc);
    store_row64(g_k + (size_t)t0 * 64, acc);
    __syncthreads();
    for (int i = tid; i < 4096; i += 256) s_w[i] = Wv[i];
    __syncthreads();
    mm64(hrow, s_w, bv, acc);
    store_row64(g_v + (size_t)t0 * 64, acc);
}

// ---------------- kernel 3: attention + Wo + LN1 (2-head interleave, 3 blk/SM) ----------------
#define SKV 68
#define ATT_SMEM ((128*SKV*2) * 4)

__global__ void __launch_bounds__(128, 3) pcv_attn(
    const float* __restrict__ Wo, const float* __restrict__ bo,
    const float* __restrict__ ln1_g, const float* __restrict__ ln1_b)
{
    extern __shared__ float sm[];
    float* s_k = sm;
    float* s_v = sm + 128 * SKV;
    float* s_w = s_v;   // Wo overlaid into s_v after attention phase

    int n = blockIdx.x;
    int p = threadIdx.x;
    int t0 = n * 128 + p;

    const float4* gk = reinterpret_cast<const float4*>(g_k + (size_t)n * 128 * 64);
    const float4* gv = reinterpret_cast<const float4*>(g_v + (size_t)n * 128 * 64);
    for (int e = p; e < 2048; e += 128) {
        int row = e >> 4, c4 = e & 15;
        *reinterpret_cast<float4*>(s_k + row * SKV + c4 * 4) = gk[e];
        *reinterpret_cast<float4*>(s_v + row * SKV + c4 * 4) = gv[e];
    }
    __syncthreads();

    float arow[64];
#pragma unroll
    for (int hp = 0; hp < 2; hp++) {
        int h0 = hp * 2;
        float qh0[16], qh1[16];
        const float4* qg = reinterpret_cast<const float4*>(g_q + (size_t)t0 * 64 + h0 * 16);
#pragma unroll
        for (int j4 = 0; j4 < 4; j4++) {
            float4 a = qg[j4];
            qh0[j4*4] = a.x; qh0[j4*4+1] = a.y; qh0[j4*4+2] = a.z; qh0[j4*4+3] = a.w;
        }
#pragma unroll
        for (int j4 = 0; j4 < 4; j4++) {
            float4 a = qg[4 + j4];
            qh1[j4*4] = a.x; qh1[j4*4+1] = a.y; qh1[j4*4+2] = a.z; qh1[j4*4+3] = a.w;
        }
        float m0 = -1e30f, l0 = 0.f, m1 = -1e30f, l1 = 0.f;
        float o0[16], o1[16];
#pragma unroll
        for (int j = 0; j < 16; j++) { o0[j] = 0.f; o1[j] = 0.f; }

        for (int pk = 0; pk < 128; pk++) {
            const float4* kr = reinterpret_cast<const float4*>(s_k + pk * SKV + h0 * 16);
            float s0 = 0.f, s1 = 0.f;
#pragma unroll
            for (int j4 = 0; j4 < 4; j4++) {
                float4 kv = kr[j4];
                s0 += qh0[j4*4+0]*kv.x + qh0[j4*4+1]*kv.y
                    + qh0[j4*4+2]*kv.z + qh0[j4*4+3]*kv.w;
            }
#pragma unroll
            for (int j4 = 0; j4 < 4; j4++) {
                float4 kv = kr[4 + j4];
                s1 += qh1[j4*4+0]*kv.x + qh1[j4*4+1]*kv.y
                    + qh1[j4*4+2]*kv.z + qh1[j4*4+3]*kv.w;
            }
            s0 *= 0.25f; s1 *= 0.25f;
            float mn0 = fmaxf(m0, s0), mn1 = fmaxf(m1, s1);
            float c0 = __expf(m0 - mn0), c1 = __expf(m1 - mn1);
            float w0 = __expf(s0 - mn0), w1 = __expf(s1 - mn1);
            l0 = l0 * c0 + w0;
            l1 = l1 * c1 + w1;
            const float4* vr = reinterpret_cast<const float4*>(s_v + pk * SKV + h0 * 16);
#pragma unroll
            for (int j4 = 0; j4 < 4; j4++) {
                float4 vv = vr[j4];
                o0[j4*4+0] = o0[j4*4+0] * c0 + w0 * vv.x;
                o0[j4*4+1] = o0[j4*4+1] * c0 + w0 * vv.y;
                o0[j4*4+2] = o0[j4*4+2] * c0 + w0 * vv.z;
                o0[j4*4+3] = o0[j4*4+3] * c0 + w0 * vv.w;
            }
#pragma unroll
            for (int j4 = 0; j4 < 4; j4++) {
                float4 vv = vr[4 + j4];
                o1[j4*4+0] = o1[j4*4+0] * c1 + w1 * vv.x;
                o1[j4*4+1] = o1[j4*4+1] * c1 + w1 * vv.y;
                o1[j4*4+2] = o1[j4*4+2] * c1 + w1 * vv.z;
                o1[j4*4+3] = o1[j4*4+3] * c1 + w1 * vv.w;
            }
            m0 = mn0; m1 = mn1;
        }
        float inv0 = 1.0f / l0, inv1 = 1.0f / l1;
#pragma unroll
        for (int j = 0; j < 16; j++) {
            arow[h0 * 16 + j]      = o0[j] * inv0;
            arow[h0 * 16 + 16 + j] = o1[j] * inv1;
        }
    }
    __syncthreads();   // all threads done reading s_k / s_v

    // stage arow in own s_k row; load Wo into s_v region
    store_row64(s_k + p * SKV, arow);
    for (int i = p; i < 4096; i += 128) s_w[i] = Wo[i];
    __syncthreads();

    float acc[64];
    mm64(s_k + p * SKV, s_w, bo, acc);

    float hreg[64];
    load_row64(hreg, g_h + (size_t)t0 * 64);
    float hn[64];
    float msum = 0.f;
#pragma unroll
    for (int d = 0; d < 64; d++) { hn[d] = hreg[d] + acc[d]; msum += hn[d]; }
    float mu = msum * (1.0f / 64);
    float vs = 0.f;
#pragma unroll
    for (int d = 0; d < 64; d++) { float df = hn[d] - mu; vs += df * df; }
    float rs = 1.0f / sqrtf(vs * (1.0f / 64) + EPSF);
#pragma unroll
    for (int d = 0; d < 64; d++) hn[d] = (hn[d] - mu) * rs * ln1_g[d] + ln1_b[d];

    store_row64(g_q + (size_t)t0 * 64, hn);
}

// ---------------- kernel 4: FFN + residual + LN2 (k-unrolled x4 chains) ----------------
#define FFN_SMEM ((128*64*2) * 4)

__global__ void __launch_bounds__(128, 3) pcv_ffn(
    const float* __restrict__ W1, const float* __restrict__ b1,
    const float* __restrict__ W2, const float* __restrict__ b2,
    const float* __restrict__ ln2_g, const float* __restrict__ ln2_b)
{
    extern __shared__ float sm[];
    float* s_w1t = sm;
    float* s_w2  = sm + 128 * 64;

    int tid = threadIdx.x;
    int t = blockIdx.x * 128 + tid;

    float hn[64];
    load_row64(hn, g_q + (size_t)t * 64);

    float acc[64];
#pragma unroll
    for (int d = 0; d < 64; d++) acc[d] = b2[d];

    for (int h = 0; h < 2; h++) {
        if (h) __syncthreads();
        for (int i = tid; i < 128 * 64; i += 128) {
            int kk = i >> 6, j = i & 63;
            s_w1t[i] = W1[j * 256 + h * 128 + kk];
        }
        for (int i = tid; i < 128 * 64; i += 128) s_w2[i] = W2[h * 8192 + i];
        __syncthreads();
        for (int k = 0; k < 128; k += 4) {
            float f0 = b1[h * 128 + k + 0];
            float f1 = b1[h * 128 + k + 1];
            float f2 = b1[h * 128 + k + 2];
            float f3 = b1[h * 128 + k + 3];
            const float4* c0 = reinterpret_cast<const float4*>(s_w1t + (k + 0) * 64);
            const float4* c1 = reinterpret_cast<const float4*>(s_w1t + (k + 1) * 64);
            const float4* c2 = reinterpret_cast<const float4*>(s_w1t + (k + 2) * 64);
            const float4* c3 = reinterpret_cast<const float4*>(s_w1t + (k + 3) * 64);
#pragma unroll
            for (int j4 = 0; j4 < 16; j4++) {
                float4 a = c0[j4], bb = c1[j4], cc = c2[j4], dd = c3[j4];
                float h0 = hn[j4*4+0], h1v = hn[j4*4+1], h2 = hn[j4*4+2], h3 = hn[j4*4+3];
                f0 += h0 * a.x  + h1v * a.y  + h2 * a.z  + h3 * a.w;
                f1 += h0 * bb.x + h1v * bb.y + h2 * bb.z + h3 * bb.w;
                f2 += h0 * cc.x + h1v * cc.y + h2 * cc.z + h3 * cc.w;
                f3 += h0 * dd.x + h1v * dd.y + h2 * dd.z + h3 * dd.w;
            }
            f0 = fmaxf(f0, 0.f); f1 = fmaxf(f1, 0.f);
            f2 = fmaxf(f2, 0.f); f3 = fmaxf(f3, 0.f);
            float fs[4] = {f0, f1, f2, f3};
#pragma unroll
            for (int u = 0; u < 4; u++) {
                float f = fs[u];
                const float4* w2r = reinterpret_cast<const float4*>(s_w2 + (k + u) * 64);
#pragma unroll
                for (int d4 = 0; d4 < 16; d4++) {
                    float4 ww = w2r[d4];
                    acc[d4 * 4 + 0] += f * ww.x;
                    acc[d4 * 4 + 1] += f * ww.y;
                    acc[d4 * 4 + 2] += f * ww.z;
                    acc[d4 * 4 + 3] += f * ww.w;
                }
            }
        }
    }

    float msum = 0.f;
#pragma unroll
    for (int d = 0; d < 64; d++) { acc[d] += hn[d]; msum += acc[d]; }
    float mu = msum * (1.0f / 64);
    float vs = 0.f;
#pragma unroll
    for (int d = 0; d < 64; d++) { float df = acc[d] - mu; vs += df * df; }
    float rs = 1.0f / sqrtf(vs * (1.0f / 64) + EPSF);
    float zr[64];
#pragma unroll
    for (int d = 0; d < 64; d++) zr[d] = (acc[d] - mu) * rs * ln2_g[d] + ln2_b[d];
    store_row64(g_z + (size_t)t * 64, zr);
}

// ---------------- kernel 5: quantizer (2 tokens/thread, kk-unrolled x2) ----------------
#define QNT_SMEM2 ((128*64 + 128) * 4)

__global__ void __launch_bounds__(128, 3) pcv_quant(const float* __restrict__ codebook,
                                                    float* __restrict__ out)
{
    extern __shared__ float sm[];
    float* s_cb = sm;
    float* s_e2 = sm + 128 * 64;
    __shared__ float red[128];
    int tid = threadIdx.x;
    int tA = blockIdx.x * 256 + tid;
    int tB = tA + 128;

    float zA[64], zB[64];
    load_row64(zA, g_z + (size_t)tA * 64);
    load_row64(zB, g_z + (size_t)tB * 64);
    float z2A = 0.f, z2B = 0.f;
#pragma unroll
    for (int j = 0; j < 64; j++) z2A += zA[j] * zA[j];
#pragma unroll
    for (int j = 0; j < 64; j++) z2B += zB[j] * zB[j];

    float bestA = 3.4e38f, bestB = 3.4e38f;
    int biA = 0, biB = 0;

    for (int cch = 0; cch < 4; cch++) {
        if (cch) __syncthreads();
        for (int i = tid; i < 128 * 64; i += 128) s_cb[i] = codebook[cch * 8192 + i];
        __syncthreads();
        {
            const float* cr = s_cb + tid * 64;
            float s = 0.f;
#pragma unroll 8
            for (int j = 0; j < 64; j++) s += cr[j] * cr[j];
            s_e2[tid] = s;
        }
        __syncthreads();
        for (int kk = 0; kk < 128; kk += 2) {
            const float4* cr0 = reinterpret_cast<const float4*>(s_cb + kk * 64);
            const float4* cr1 = reinterpret_cast<const float4*>(s_cb + (kk + 1) * 64);
            float dA0 = 0.f, dB0 = 0.f, dA1 = 0.f, dB1 = 0.f;
#pragma unroll
            for (int j4 = 0; j4 < 16; j4++) {
                float4 c0 = cr0[j4];
                float4 c1 = cr1[j4];
                dA0 += zA[j4 * 4 + 0] * c0.x;
                dA0 += zA[j4 * 4 + 1] * c0.y;
                dA0 += zA[j4 * 4 + 2] * c0.z;
                dA0 += zA[j4 * 4 + 3] * c0.w;
                dB0 += zB[j4 * 4 + 0] * c0.x;
                dB0 += zB[j4 * 4 + 1] * c0.y;
                dB0 += zB[j4 * 4 + 2] * c0.z;
                dB0 += zB[j4 * 4 + 3] * c0.w;
                dA1 += zA[j4 * 4 + 0] * c1.x;
                dA1 += zA[j4 * 4 + 1] * c1.y;
                dA1 += zA[j4 * 4 + 2] * c1.z;
                dA1 += zA[j4 * 4 + 3] * c1.w;
                dB1 += zB[j4 * 4 + 0] * c1.x;
                dB1 += zB[j4 * 4 + 1] * c1.y;
                dB1 += zB[j4 * 4 + 2] * c1.z;
                dB1 += zB[j4 * 4 + 3] * c1.w;
            }
            float e20 = s_e2[kk], e21 = s_e2[kk + 1];
            int kg = cch * 128 + kk;
            float d0A = __fadd_rn(__fadd_rn(z2A, e20), -__fmul_rn(2.0f, dA0));
            float d0B = __fadd_rn(__fadd_rn(z2B, e20), -__fmul_rn(2.0f, dB0));
            if (d0A < bestA) { bestA = d0A; biA = kg; }
            if (d0B < bestB) { bestB = d0B; biB = kg; }
            float d1A = __fadd_rn(__fadd_rn(z2A, e21), -__fmul_rn(2.0f, dA1));
            float d1B = __fadd_rn(__fadd_rn(z2B, e21), -__fmul_rn(2.0f, dB1));
            if (d1A < bestA) { bestA = d1A; biA = kg + 1; }
            if (d1B < bestB) { bestB = d1B; biB = kg + 1; }
        }
    }

    {
        float2* zqo = reinterpret_cast<float2*>(out + OFF_ZQ + (size_t)tA * 64);
        const float2* cb2 = reinterpret_cast<const float2*>(codebook + (size_t)biA * 64);
#pragma unroll
        for (int j = 0; j < 32; j++) zqo[j] = cb2[j];
    }
    {
        float2* zqo = reinterpret_cast<float2*>(out + OFF_ZQ + (size_t)tB * 64);
        const float2* cb2 = reinterpret_cast<const float2*>(codebook + (size_t)biB * 64);
#pragma unroll
        for (int j = 0; j < 32; j++) zqo[j] = cb2[j];
    }
    out[OFF_IDX + tA] = (float)biA;
    out[OFF_IDX + tB] = (float)biB;
    atomicAdd(&g_counts[biA], 1);
    atomicAdd(&g_counts[biB], 1);

    red[tid] = bestA + bestB;
    __syncthreads();
    for (int s = 64; s > 0; s >>= 1) {
        if (tid < s) red[tid] += red[tid + s];
        __syncthreads();
    }
    if (tid == 0) g_sq_partial[blockIdx.x] = red[0];
}

// ---------------- kernel 6: decode the 512 codewords once ----------------
#define DEC_SMEM ((256*64 + 256*16 + 64*16) * 4)

__global__ __launch_bounds__(256) void pcv_deccb(
    const float* __restrict__ codebook,
    const float* __restrict__ dW1, const float* __restrict__ db1,
    const float* __restrict__ dW2, const float* __restrict__ db2,
    const float* __restrict__ dWr, const float* __restrict__ dbr,
    const float* __restrict__ lng, const float* __restrict__ lnb)
{
    extern __shared__ float sm[];
    float* s_w1t = sm;
    float* s_w2  = sm + 256 * 64;
    float* s_wr  = s_w2 + 256 * 16;
    int tid = threadIdx.x;
    for (int i = tid; i < 64 * 256; i += 256) {
        int j = i >> 8, k = i & 255;
        s_w1t[k * 64 + j] = dW1[i];
    }
    for (int i = tid; i < 256 * 16; i += 256) s_w2[i] = dW2[i];
    for (int i = tid; i < 64 * 16; i += 256)  s_wr[i] = dWr[i];
    __syncthreads();

    int cw = blockIdx.x * 256 + tid;

    float zq[64];
    const float2* cb2 = reinterpret_cast<const float2*>(codebook + (size_t)cw * 64);
#pragma unroll
    for (int j = 0; j < 32; j++) { float2 v = cb2[j]; zq[2 * j] = v.x; zq[2 * j + 1] = v.y; }

    float y[16];
#pragma unroll
    for (int i = 0; i < 16; i++) y[i] = db2[i];
    for (int k = 0; k < 256; k++) {
        const float4* w1c = reinterpret_cast<const float4*>(s_w1t + k * 64);
        float f = db1[k];
#pragma unroll
        for (int j4 = 0; j4 < 16; j4++) {
            float4 w = w1c[j4];
            f += zq[j4 * 4 + 0] * w.x + zq[j4 * 4 + 1] * w.y
               + zq[j4 * 4 + 2] * w.z + zq[j4 * 4 + 3] * w.w;
        }
        f = fmaxf(f, 0.f);
        const float4* w2r = reinterpret_cast<const float4*>(s_w2 + k * 16);
#pragma unroll
        for (int i4 = 0; i4 < 4; i4++) {
            float4 w = w2r[i4];
            y[i4 * 4 + 0] += f * w.x;
            y[i4 * 4 + 1] += f * w.y;
            y[i4 * 4 + 2] += f * w.z;
            y[i4 * 4 + 3] += f * w.w;
        }
    }
#pragma unroll
    for (int i = 0; i < 16; i++) y[i] += dbr[i];
#pragma unroll 8
    for (int j = 0; j < 64; j++) {
        float zj = zq[j];
        const float4* wr4 = reinterpret_cast<const float4*>(s_wr + j * 16);
#pragma unroll
        for (int i4 = 0; i4 < 4; i4++) {
            float4 w = wr4[i4];
            y[i4 * 4 + 0] += zj * w.x;
            y[i4 * 4 + 1] += zj * w.y;
            y[i4 * 4 + 2] += zj * w.z;
            y[i4 * 4 + 3] += zj * w.w;
        }
    }
    float mu = 0.f;
#pragma unroll
    for (int i = 0; i < 16; i++) mu += y[i];
    mu *= (1.0f / 16);
    float var = 0.f;
#pragma unroll
    for (int i = 0; i < 16; i++) { float d = y[i] - mu; var += d * d; }
    var *= (1.0f / 16);
    float rs = 1.0f / sqrtf(var + EPSF);
#pragma unroll
    for (int i = 0; i < 16; i++)
        g_rec[cw * 16 + i] = (y[i] - mu) * rs * lng[i] + lnb[i];
}

// ---------------- kernel 7: gather + denorm + rec-loss ----------------
__global__ __launch_bounds__(256) void pcv_apply(
    const float* __restrict__ x,
    const float* __restrict__ revin_w, const float* __restrict__ revin_b,
    float* __restrict__ out)
{
    __shared__ float s_rec[Kk * PLn];
    __shared__ float red[256];
    int tid = threadIdx.x;
    for (int i = tid; i < Kk * PLn; i += 256) s_rec[i] = g_rec[i];
    __syncthreads();

    int c = tid & 31;
    int rgrp = tid >> 5;
    float rwc = revin_w[c] + 1e-10f;
    float rbc = revin_b[c];
    float local = 0.f;
#pragma unroll 4
    for (int it = 0; it < 16; it++) {
        int row = blockIdx.x * 128 + it * 8 + rgrp;
        int b = row >> 11;
        int l = row & 2047;
        int pp = l >> 4, i = l & 15;
        int n = b * 32 + c;
        int idx = (int)out[OFF_IDX + (size_t)n * 128 + pp];
        float rec = s_rec[idx * 16 + i];
        float rv = (rec - rbc) / rwc * g_std[n] + g_mean[n];
        size_t off = (size_t)row * 32 + c;
        out[OFF_R + off] = rv;
        float dx = x[off] - rv;
        local += dx * dx;
    }
    red[tid] = local;
    __syncthreads();
    for (int s = 128; s > 0; s >>= 1) {
        if (tid < s) red[tid] += red[tid + s];
        __syncthreads();
    }
    if (tid == 0) g_rec_partial[blockIdx.x] = red[0];
}

// ---------------- kernel 8: finalize scalars ----------------
__global__ void pcv_final(float* __restrict__ out)
{
    if (threadIdx.x == 0 && blockIdx.x == 0) {
        float sq = 0.f;
        for (int i = 0; i < 512; i++) sq += g_sq_partial[i];
        float recs = 0.f;
        for (int i = 0; i < 512; i++) recs += g_rec_partial[i];
        float mse = sq * (1.0f / 8388608.0f);
        float cluster = mse + 0.25f * mse;
        float rec_loss = recs * (1.0f / 2097152.0f);
        out[0] = rec_loss + 0.2f * cluster;
        out[1] = rec_loss;
        float tot = 0.f;
        for (int k = 0; k < Kk; k++) tot += (float)g_counts[k];
        float inv = 1.0f / (tot + EPSF);
        float ent = 0.f;
        for (int k = 0; k < Kk; k++) {
            float pr = (float)g_counts[k] * inv;
            ent += pr * logf(pr + EPSF);
        }
        out[OFF_PERP] = expf(-ent);
    }
}

// ---------------- launch ----------------
extern "C" void kernel_launch(void* const* d_in, const int* in_sizes, int n_in,
                              void* d_out, int out_size)
{
    const float* x       = (const float*)d_in[0];
    const float* revin_w = (const float*)d_in[1];
    const float* revin_b = (const float*)d_in[2];
    const float* inp_W   = (const float*)d_in[3];
    const float* inp_b   = (const float*)d_in[4];
    const float* Wq = (const float*)d_in[5];  const float* bq = (const float*)d_in[6];
    const float* Wk = (const float*)d_in[7];  const float* bk = (const float*)d_in[8];
    const float* Wv = (const float*)d_in[9];  const float* bv = (const float*)d_in[10];
    const float* Wo = (const float*)d_in[11]; const float* bo = (const float*)d_in[12];
    const float* ln1_g = (const float*)d_in[13]; const float* ln1_b = (const float*)d_in[14];
    const float* W1 = (const float*)d_in[15]; const float* b1 = (const float*)d_in[16];
    const float* W2 = (const float*)d_in[17]; const float* b2 = (const float*)d_in[18];
    const float* ln2_g = (const float*)d_in[19]; const float* ln2_b = (const float*)d_in[20];
    const float* codebook = (const float*)d_in[21];
    const float* dW1 = (const float*)d_in[22]; const float* db1 = (const float*)d_in[23];
    const float* dW2 = (const float*)d_in[24]; const float* db2 = (const float*)d_in[25];
    const float* dWr = (const float*)d_in[26]; const float* dbr = (const float*)d_in[27];
    const float* dlg = (const float*)d_in[28]; const float* dlb = (const float*)d_in[29];
    float* out = (float*)d_out;

    cudaFuncSetAttribute(pcv_qkvh,  cudaFuncAttributeMaxDynamicSharedMemorySize, QKV_SMEM);
    cudaFuncSetAttribute(pcv_attn,  cudaFuncAttributeMaxDynamicSharedMemorySize, ATT_SMEM);
    cudaFuncSetAttribute(pcv_ffn,   cudaFuncAttributeMaxDynamicSharedMemorySize, FFN_SMEM);
    cudaFuncSetAttribute(pcv_quant, cudaFuncAttributeMaxDynamicSharedMemorySize, QNT_SMEM2);
    cudaFuncSetAttribute(pcv_deccb, cudaFuncAttributeMaxDynamicSharedMemorySize, DEC_SMEM);

    pcv_revin<<<Bn, 256>>>(x);
    pcv_deccb<<<2, 256, DEC_SMEM>>>(codebook, dW1, db1, dW2, db2, dWr, dbr, dlg, dlb);
    pcv_qkvh<<<NTOK / 256, 256, QKV_SMEM>>>(x, revin_w, revin_b, inp_W, inp_b,
                                            Wq, bq, Wk, bk, Wv, bv);
    pcv_attn<<<NSEQ, 128, ATT_SMEM>>>(Wo, bo, ln1_g, ln1_b);
    pcv_ffn<<<NTOK / 128, 128, FFN_SMEM>>>(W1, b1, W2, b2, ln2_g, ln2_b);
    pcv_quant<<<NTOK / 256, 128, QNT_SMEM2>>>(codebook, out);
    pcv_apply<<<512, 256>>>(x, revin_w, revin_b, out);
    pcv_final<<<1, 32>>>(out);
}

// round 9
// speedup vs baseline: 1.3402x; 1.0326x over previous
#include <cuda_runtime.h>
#include <math.h>
#include <stdint.h>

// ---------------- problem constants ----------------
#define Bn   32
#define Ln   2048
#define Cn   32
#define PLn  16
#define Pp   128
#define Dd   64
#define Hh   256
#define Kk   512
#define NSEQ (Bn*Cn)        // 1024
#define NTOK (NSEQ*Pp)      // 131072
#define EPSF 1e-5f

// output layout (flattened reference return tuple, float32)
#define OFF_ZQ   ((size_t)2)
#define OFF_R    (OFF_ZQ + (size_t)NTOK*Dd)            // 8388610
#define OFF_IDX  (OFF_R + (size_t)Bn*Ln*Cn)            // 10485762
#define OFF_PERP (OFF_IDX + (size_t)NTOK)              // 10616834

// ---------------- device scratch ----------------
__device__ float g_mean[NSEQ];
__device__ float g_std[NSEQ];
__device__ float g_h[(size_t)NTOK*Dd];
__device__ float g_q[(size_t)NTOK*Dd];      // q, later reused as hn (post-LN1)
__device__ float g_k[(size_t)NTOK*Dd];
__device__ float g_v[(size_t)NTOK*Dd];
__device__ float g_z[(size_t)NTOK*Dd];
__device__ int   g_counts[Kk];
__device__ float g_sq_partial[512];
__device__ float g_rec_partial[512];
__device__ float g_rec[Kk*PLn];

// ---------------- packed f32x2 helpers (each lane = independent fma.rn) ----------------
__device__ __forceinline__ unsigned long long pk2(float lo, float hi)
{
    unsigned long long r;
    asm("mov.b64 %0,{%1,%2};" : "=l"(r) : "f"(lo), "f"(hi));
    return r;
}
__device__ __forceinline__ void upk2(unsigned long long v, float& lo, float& hi)
{
    asm("mov.b64 {%0,%1},%2;" : "=f"(lo), "=f"(hi) : "l"(v));
}
__device__ __forceinline__ unsigned long long fma2_(unsigned long long a,
                                                    unsigned long long b,
                                                    unsigned long long c)
{
    unsigned long long d;
    asm("fma.rn.f32x2 %0,%1,%2,%3;" : "=l"(d) : "l"(a), "l"(b), "l"(c));
    return d;
}

// acc2[32] (64 outputs) += hk * wrow[0..63]   — bit-identical to scalar axpy
__device__ __forceinline__ void axpy64_p(unsigned long long* acc2, float hk,
                                         const float* __restrict__ wrow)
{
    unsigned long long hk2 = pk2(hk, hk);
    const ulonglong2* w2 = reinterpret_cast<const ulonglong2*>(wrow);
#pragma unroll
    for (int i = 0; i < 16; i++) {
        ulonglong2 ww = w2[i];
        acc2[2*i]   = fma2_(hk2, ww.x, acc2[2*i]);
        acc2[2*i+1] = fma2_(hk2, ww.y, acc2[2*i+1]);
    }
}
// acc2[16] (32 outputs) += hk * wrow[0..31]
__device__ __forceinline__ void axpy32_p(unsigned long long* acc2, float hk,
                                         const float* __restrict__ wrow)
{
    unsigned long long hk2 = pk2(hk, hk);
    const ulonglong2* w2 = reinterpret_cast<const ulonglong2*>(wrow);
#pragma unroll
    for (int i = 0; i < 8; i++) {
        ulonglong2 ww = w2[i];
        acc2[2*i]   = fma2_(hk2, ww.x, acc2[2*i]);
        acc2[2*i+1] = fma2_(hk2, ww.y, acc2[2*i+1]);
    }
}

// packed 64x64 row-matmul: acc[d] = bias[d] + sum_k hrow[k]*w[k*64+d]
__device__ __forceinline__ void mm64_p(const float* __restrict__ hrow,
                                       const float* __restrict__ w,
                                       const float* __restrict__ bias,
                                       float* acc)
{
    unsigned long long a2[32];
#pragma unroll
    for (int i = 0; i < 32; i++) a2[i] = pk2(bias[2*i], bias[2*i+1]);
#pragma unroll 4
    for (int k = 0; k < 64; k++) axpy64_p(a2, hrow[k], w + k * 64);
#pragma unroll
    for (int i = 0; i < 32; i++) upk2(a2[i], acc[2*i], acc[2*i+1]);
}

__device__ __forceinline__ void store_row64(float* dst, const float* v)
{
    float4* d4 = reinterpret_cast<float4*>(dst);
#pragma unroll
    for (int j = 0; j < 16; j++)
        d4[j] = make_float4(v[4*j], v[4*j+1], v[4*j+2], v[4*j+3]);
}

__device__ __forceinline__ void load_row64(float* v, const float* src)
{
    const float4* s4 = reinterpret_cast<const float4*>(src);
#pragma unroll
    for (int j = 0; j < 16; j++) {
        float4 t = s4[j];
        v[4*j] = t.x; v[4*j+1] = t.y; v[4*j+2] = t.z; v[4*j+3] = t.w;
    }
}

// ---------------- kernel 1: RevIN stats + zero counts ----------------
__global__ __launch_bounds__(256) void pcv_revin(const float* __restrict__ x)
{
    int b = blockIdx.x;
    int t = threadIdx.x;
    int c = t & 31;
    int g = t >> 5;
    if (b == 0) {
        for (int i = t; i < Kk; i += 256) g_counts[i] = 0;
    }
    float s = 0.f, s2 = 0.f;
    const float* xb = x + (size_t)b * Ln * Cn + c;
    for (int l = g; l < Ln; l += 8) {
        float v = xb[(size_t)l * Cn];
        s += v; s2 += v * v;
    }
    __shared__ float sh_s[256], sh_q[256];
    sh_s[t] = s; sh_q[t] = s2;
    __syncthreads();
    if (g == 0) {
        float ss = 0.f, qq = 0.f;
#pragma unroll
        for (int i = 0; i < 8; i++) { ss += sh_s[i * 32 + c]; qq += sh_q[i * 32 + c]; }
        float mean = ss * (1.0f / Ln);
        float var  = qq * (1.0f / Ln) - mean * mean;
        g_mean[b * 32 + c] = mean;
        g_std [b * 32 + c] = sqrtf(var + EPSF);
    }
}

// ---------------- kernel 2: embed + Q/K/V (packed f32x2) ----------------
#define QKV_SMEM ((256*65 + 64*64) * 4)

__global__ void __launch_bounds__(256, 2) pcv_qkvh(
    const float* __restrict__ x,
    const float* __restrict__ revin_w, const float* __restrict__ revin_b,
    const float* __restrict__ inp_W,   const float* __restrict__ inp_b,
    const float* __restrict__ Wq, const float* __restrict__ bq,
    const float* __restrict__ Wk, const float* __restrict__ bk,
    const float* __restrict__ Wv, const float* __restrict__ bv)
{
    extern __shared__ float sm[];
    float* s_h = sm;
    float* s_w = sm + 256 * 65;

    int tid = threadIdx.x;
    int t0  = blockIdx.x * 256 + tid;
    int n = t0 >> 7, p = t0 & 127;
    int b = n >> 5, c = n & 31;

    float mean = g_mean[n];
    float istd = 1.0f / g_std[n];
    float rw = revin_w[c], rb = revin_b[c];
    float* hrow = s_h + tid * 65;

    for (int i = tid; i < 16 * 64; i += 256) s_w[i] = inp_W[i];
    __syncthreads();

    float acc[64];
    {   // packed embed: per-d chain identical to scalar version
        unsigned long long a2[32];
#pragma unroll
        for (int i = 0; i < 32; i++) a2[i] = pk2(inp_b[2*i], inp_b[2*i+1]);
        const float* xp = x + ((size_t)b * Ln + (size_t)p * PLn) * Cn + c;
#pragma unroll
        for (int j = 0; j < 16; j++) {
            float xv = (xp[(size_t)j * Cn] - mean) * istd * rw + rb;
            axpy64_p(a2, xv, s_w + j * 64);
        }
#pragma unroll
        for (int i = 0; i < 32; i++) upk2(a2[i], acc[2*i], acc[2*i+1]);
    }
#pragma unroll
    for (int d = 0; d < 64; d++) hrow[d] = acc[d];
    store_row64(g_h + (size_t)t0 * 64, acc);
    __syncthreads();

    for (int i = tid; i < 4096; i += 256) s_w[i] = Wq[i];
    __syncthreads();
    mm64_p(hrow, s_w, bq, acc);
    store_row64(g_q + (size_t)t0 * 64, acc);
    __syncthreads();
    for (int i = tid; i < 4096; i += 256) s_w[i] = Wk[i];
    __syncthreads();
    mm64_p(hrow, s_w, bk, acc);
    store_row64(g_k + (size_t)t0 * 64, acc);
    __syncthreads();
    for (int i = tid; i < 4096; i += 256) s_w[i] = Wv[i];
    __syncthreads();
    mm64_p(hrow, s_w, bv, acc);
    store_row64(g_v + (size_t)t0 * 64, acc);
}

// ---------------- kernel 3: attention + Wo + LN1 (256 thr, 2 heads/thread) ----------------
#define SKV 68
#define ATT_SMEM ((128*SKV*2) * 4)

__global__ void __launch_bounds__(256, 2) pcv_attn(
    const float* __restrict__ Wo, const float* __restrict__ bo,
    const float* __restrict__ ln1_g, const float* __restrict__ ln1_b)
{
    extern __shared__ float sm[];
    float* s_k = sm;
    float* s_v = sm + 128 * SKV;
    float* s_a = s_k;   // arow / acc staging overlays s_k (stride 65, conflict-free)
    float* s_w = s_v;   // Wo overlays s_v after attention phase

    int n = blockIdx.x;
    int tid = threadIdx.x;
    int p  = tid & 127;      // token
    int hp = tid >> 7;       // head pair 0/1
    int h0 = hp * 2;
    int t0 = n * 128 + p;

    const float4* gk = reinterpret_cast<const float4*>(g_k + (size_t)n * 128 * 64);
    const float4* gv = reinterpret_cast<const float4*>(g_v + (size_t)n * 128 * 64);
    for (int e = tid; e < 2048; e += 256) {
        int row = e >> 4, c4 = e & 15;
        *reinterpret_cast<float4*>(s_k + row * SKV + c4 * 4) = gk[e];
        *reinterpret_cast<float4*>(s_v + row * SKV + c4 * 4) = gv[e];
    }
    __syncthreads();

    // q for this thread's 2 heads
    float qh0[16], qh1[16];
    {
        const float4* qg = reinterpret_cast<const float4*>(g_q + (size_t)t0 * 64 + h0 * 16);
#pragma unroll
        for (int j4 = 0; j4 < 4; j4++) {
            float4 a = qg[j4];
            qh0[j4*4] = a.x; qh0[j4*4+1] = a.y; qh0[j4*4+2] = a.z; qh0[j4*4+3] = a.w;
        }
#pragma unroll
        for (int j4 = 0; j4 < 4; j4++) {
            float4 a = qg[4 + j4];
            qh1[j4*4] = a.x; qh1[j4*4+1] = a.y; qh1[j4*4+2] = a.z; qh1[j4*4+3] = a.w;
        }
    }
    float m0 = -1e30f, l0 = 0.f, m1 = -1e30f, l1 = 0.f;
    float o0[16], o1[16];
#pragma unroll
    for (int j = 0; j < 16; j++) { o0[j] = 0.f; o1[j] = 0.f; }

    // --- attention (identical per-head math to previous rounds) ---
    for (int pk = 0; pk < 128; pk++) {
        const float4* kr = reinterpret_cast<const float4*>(s_k + pk * SKV + h0 * 16);
        float s0 = 0.f, s1 = 0.f;
#pragma unroll
        for (int j4 = 0; j4 < 4; j4++) {
            float4 kv = kr[j4];
            s0 += qh0[j4*4+0]*kv.x + qh0[j4*4+1]*kv.y
                + qh0[j4*4+2]*kv.z + qh0[j4*4+3]*kv.w;
        }
#pragma unroll
        for (int j4 = 0; j4 < 4; j4++) {
            float4 kv = kr[4 + j4];
            s1 += qh1[j4*4+0]*kv.x + qh1[j4*4+1]*kv.y
                + qh1[j4*4+2]*kv.z + qh1[j4*4+3]*kv.w;
        }
        s0 *= 0.25f; s1 *= 0.25f;
        float mn0 = fmaxf(m0, s0), mn1 = fmaxf(m1, s1);
        float c0 = __expf(m0 - mn0), c1 = __expf(m1 - mn1);
        float w0 = __expf(s0 - mn0), w1 = __expf(s1 - mn1);
        l0 = l0 * c0 + w0;
        l1 = l1 * c1 + w1;
        const float4* vr = reinterpret_cast<const float4*>(s_v + pk * SKV + h0 * 16);
#pragma unroll
        for (int j4 = 0; j4 < 4; j4++) {
            float4 vv = vr[j4];
            o0[j4*4+0] = o0[j4*4+0] * c0 + w0 * vv.x;
            o0[j4*4+1] = o0[j4*4+1] * c0 + w0 * vv.y;
            o0[j4*4+2] = o0[j4*4+2] * c0 + w0 * vv.z;
            o0[j4*4+3] = o0[j4*4+3] * c0 + w0 * vv.w;
        }
#pragma unroll
        for (int j4 = 0; j4 < 4; j4++) {
            float4 vv = vr[4 + j4];
            o1[j4*4+0] = o1[j4*4+0] * c1 + w1 * vv.x;
            o1[j4*4+1] = o1[j4*4+1] * c1 + w1 * vv.y;
            o1[j4*4+2] = o1[j4*4+2] * c1 + w1 * vv.z;
            o1[j4*4+3] = o1[j4*4+3] * c1 + w1 * vv.w;
        }
        m0 = mn0; m1 = mn1;
    }
    float inv0 = 1.0f / l0, inv1 = 1.0f / l1;
    __syncthreads();   // all threads done reading s_k / s_v

    // stage arow halves (stride-65 rows); load Wo into s_v region
    {
        float* ar = s_a + p * 65 + hp * 32;
#pragma unroll
        for (int j = 0; j < 16; j++) ar[j]      = o0[j] * inv0;
#pragma unroll
        for (int j = 0; j < 16; j++) ar[16 + j] = o1[j] * inv1;
    }
    for (int i = tid; i < 4096; i += 256) s_w[i] = Wo[i];
    __syncthreads();

    // Wo projection: this thread computes outputs d in [hp*32, hp*32+32)
    int dlo = hp * 32;
    float acch[32];
    {
        unsigned long long a2[16];
#pragma unroll
        for (int i = 0; i < 16; i++) a2[i] = pk2(bo[dlo + 2*i], bo[dlo + 2*i + 1]);
        const float* ar = s_a + p * 65;
#pragma unroll 4
        for (int k = 0; k < 64; k++) axpy32_p(a2, ar[k], s_w + k * 64 + dlo);
#pragma unroll
        for (int i = 0; i < 16; i++) upk2(a2[i], acch[2*i], acch[2*i+1]);
    }
    __syncthreads();   // everyone done reading s_a (arow)
    {
        float* ac = s_a + p * 65 + dlo;
#pragma unroll
        for (int j = 0; j < 32; j++) ac[j] = acch[j];
    }
    __syncthreads();

    // residual + LN1 by hp==0 threads (exact previous op order)
    if (hp == 0) {
        float hreg[64];
        load_row64(hreg, g_h + (size_t)t0 * 64);
        const float* ac = s_a + p * 65;
        float msum = 0.f;
#pragma unroll
        for (int d = 0; d < 64; d++) { hreg[d] = hreg[d] + ac[d]; msum += hreg[d]; }
        float mu = msum * (1.0f / 64);
        float vs = 0.f;
#pragma unroll
        for (int d = 0; d < 64; d++) { float df = hreg[d] - mu; vs += df * df; }
        float rs = 1.0f / sqrtf(vs * (1.0f / 64) + EPSF);
#pragma unroll
        for (int d = 0; d < 64; d++) hreg[d] = (hreg[d] - mu) * rs * ln1_g[d] + ln1_b[d];
        store_row64(g_q + (size_t)t0 * 64, hreg);
    }
}

// ---------------- kernel 4: FFN + residual + LN2 (packed W2-accumulate) ----------------
#define FFN_SMEM ((128*64*2) * 4)

__global__ void __launch_bounds__(128, 3) pcv_ffn(
    const float* __restrict__ W1, const float* __restrict__ b1,
    const float* __restrict__ W2, const float* __restrict__ b2,
    const float* __restrict__ ln2_g, const float* __restrict__ ln2_b)
{
    extern __shared__ float sm[];
    float* s_w1t = sm;
    float* s_w2  = sm + 128 * 64;

    int tid = threadIdx.x;
    int t = blockIdx.x * 128 + tid;

    float hn[64];
    load_row64(hn, g_q + (size_t)t * 64);

    unsigned long long acc2[32];
#pragma unroll
    for (int i = 0; i < 32; i++) acc2[i] = pk2(b2[2*i], b2[2*i+1]);

    for (int h = 0; h < 2; h++) {
        if (h) __syncthreads();
        for (int i = tid; i < 128 * 64; i += 128) {
            int kk = i >> 6, j = i & 63;
            s_w1t[i] = W1[j * 256 + h * 128 + kk];
        }
        for (int i = tid; i < 128 * 64; i += 128) s_w2[i] = W2[h * 8192 + i];
        __syncthreads();
        for (int k = 0; k < 128; k += 4) {
            float f0 = b1[h * 128 + k + 0];
            float f1 = b1[h * 128 + k + 1];
            float f2 = b1[h * 128 + k + 2];
            float f3 = b1[h * 128 + k + 3];
            const float4* c0 = reinterpret_cast<const float4*>(s_w1t + (k + 0) * 64);
            const float4* c1 = reinterpret_cast<const float4*>(s_w1t + (k + 1) * 64);
            const float4* c2 = reinterpret_cast<const float4*>(s_w1t + (k + 2) * 64);
            const float4* c3 = reinterpret_cast<const float4*>(s_w1t + (k + 3) * 64);
#pragma unroll
            for (int j4 = 0; j4 < 16; j4++) {
                float4 a = c0[j4], bb = c1[j4], cc = c2[j4], dd = c3[j4];
                float h0 = hn[j4*4+0], h1v = hn[j4*4+1], h2 = hn[j4*4+2], h3 = hn[j4*4+3];
                f0 += h0 * a.x  + h1v * a.y  + h2 * a.z  + h3 * a.w;
                f1 += h0 * bb.x + h1v * bb.y + h2 * bb.z + h3 * bb.w;
                f2 += h0 * cc.x + h1v * cc.y + h2 * cc.z + h3 * cc.w;
                f3 += h0 * dd.x + h1v * dd.y + h2 * dd.z + h3 * dd.w;
            }
            f0 = fmaxf(f0, 0.f); f1 = fmaxf(f1, 0.f);
            f2 = fmaxf(f2, 0.f); f3 = fmaxf(f3, 0.f);
            float fs[4] = {f0, f1, f2, f3};
#pragma unroll
            for (int u = 0; u < 4; u++) {
                axpy64_p(acc2, fs[u], s_w2 + (k + u) * 64);   // identical per-d chains
            }
        }
    }

    float acc[64];
#pragma unroll
    for (int i = 0; i < 32; i++) upk2(acc2[i], acc[2*i], acc[2*i+1]);

    float msum = 0.f;
#pragma unroll
    for (int d = 0; d < 64; d++) { acc[d] += hn[d]; msum += acc[d]; }
    float mu = msum * (1.0f / 64);
    float vs = 0.f;
#pragma unroll
    for (int d = 0; d < 64; d++) { float df = acc[d] - mu; vs += df * df; }
    float rs = 1.0f / sqrtf(vs * (1.0f / 64) + EPSF);
    float zr[64];
#pragma unroll
    for (int d = 0; d < 64; d++) zr[d] = (acc[d] - mu) * rs * ln2_g[d] + ln2_b[d];
    store_row64(g_z + (size_t)t * 64, zr);
}

// ---------------- kernel 5: quantizer (unchanged — argmin-critical) ----------------
#define QNT_SMEM2 ((128*64 + 128) * 4)

__global__ void __launch_bounds__(128, 3) pcv_quant(const float* __restrict__ codebook,
                                                    float* __restrict__ out)
{
    extern __shared__ float sm[];
    float* s_cb = sm;
    float* s_e2 = sm + 128 * 64;
    __shared__ float red[128];
    int tid = threadIdx.x;
    int tA = blockIdx.x * 256 + tid;
    int tB = tA + 128;

    float zA[64], zB[64];
    load_row64(zA, g_z + (size_t)tA * 64);
    load_row64(zB, g_z + (size_t)tB * 64);
    float z2A = 0.f, z2B = 0.f;
#pragma unroll
    for (int j = 0; j < 64; j++) z2A += zA[j] * zA[j];
#pragma unroll
    for (int j = 0; j < 64; j++) z2B += zB[j] * zB[j];

    float bestA = 3.4e38f, bestB = 3.4e38f;
    int biA = 0, biB = 0;

    for (int cch = 0; cch < 4; cch++) {
        if (cch) __syncthreads();
        for (int i = tid; i < 128 * 64; i += 128) s_cb[i] = codebook[cch * 8192 + i];
        __syncthreads();
        {
            const float* cr = s_cb + tid * 64;
            float s = 0.f;
#pragma unroll 8
            for (int j = 0; j < 64; j++) s += cr[j] * cr[j];
            s_e2[tid] = s;
        }
        __syncthreads();
        for (int kk = 0; kk < 128; kk += 2) {
            const float4* cr0 = reinterpret_cast<const float4*>(s_cb + kk * 64);
            const float4* cr1 = reinterpret_cast<const float4*>(s_cb + (kk + 1) * 64);
            float dA0 = 0.f, dB0 = 0.f, dA1 = 0.f, dB1 = 0.f;
#pragma unroll
            for (int j4 = 0; j4 < 16; j4++) {
                float4 c0 = cr0[j4];
                float4 c1 = cr1[j4];
                dA0 += zA[j4 * 4 + 0] * c0.x;
                dA0 += zA[j4 * 4 + 1] * c0.y;
                dA0 += zA[j4 * 4 + 2] * c0.z;
                dA0 += zA[j4 * 4 + 3] * c0.w;
                dB0 += zB[j4 * 4 + 0] * c0.x;
                dB0 += zB[j4 * 4 + 1] * c0.y;
                dB0 += zB[j4 * 4 + 2] * c0.z;
                dB0 += zB[j4 * 4 + 3] * c0.w;
                dA1 += zA[j4 * 4 + 0] * c1.x;
                dA1 += zA[j4 * 4 + 1] * c1.y;
                dA1 += zA[j4 * 4 + 2] * c1.z;
                dA1 += zA[j4 * 4 + 3] * c1.w;
                dB1 += zB[j4 * 4 + 0] * c1.x;
                dB1 += zB[j4 * 4 + 1] * c1.y;
                dB1 += zB[j4 * 4 + 2] * c1.z;
                dB1 += zB[j4 * 4 + 3] * c1.w;
            }
            float e20 = s_e2[kk], e21 = s_e2[kk + 1];
            int kg = cch * 128 + kk;
            float d0A = __fadd_rn(__fadd_rn(z2A, e20), -__fmul_rn(2.0f, dA0));
            float d0B = __fadd_rn(__fadd_rn(z2B, e20), -__fmul_rn(2.0f, dB0));
            if (d0A < bestA) { bestA = d0A; biA = kg; }
            if (d0B < bestB) { bestB = d0B; biB = kg; }
            float d1A = __fadd_rn(__fadd_rn(z2A, e21), -__fmul_rn(2.0f, dA1));
            float d1B = __fadd_rn(__fadd_rn(z2B, e21), -__fmul_rn(2.0f, dB1));
            if (d1A < bestA) { bestA = d1A; biA = kg + 1; }
            if (d1B < bestB) { bestB = d1B; biB = kg + 1; }
        }
    }

    {
        float2* zqo = reinterpret_cast<float2*>(out + OFF_ZQ + (size_t)tA * 64);
        const float2* cb2 = reinterpret_cast<const float2*>(codebook + (size_t)biA * 64);
#pragma unroll
        for (int j = 0; j < 32; j++) zqo[j] = cb2[j];
    }
    {
        float2* zqo = reinterpret_cast<float2*>(out + OFF_ZQ + (size_t)tB * 64);
        const float2* cb2 = reinterpret_cast<const float2*>(codebook + (size_t)biB * 64);
#pragma unroll
        for (int j = 0; j < 32; j++) zqo[j] = cb2[j];
    }
    out[OFF_IDX + tA] = (float)biA;
    out[OFF_IDX + tB] = (float)biB;
    atomicAdd(&g_counts[biA], 1);
    atomicAdd(&g_counts[biB], 1);

    red[tid] = bestA + bestB;
    __syncthreads();
    for (int s = 64; s > 0; s >>= 1) {
        if (tid < s) red[tid] += red[tid + s];
        __syncthreads();
    }
    if (tid == 0) g_sq_partial[blockIdx.x] = red[0];
}

// ---------------- kernel 6: decode the 512 codewords once ----------------
#define DEC_SMEM ((256*64 + 256*16 + 64*16) * 4)

__global__ __launch_bounds__(256) void pcv_deccb(
    const float* __restrict__ codebook,
    const float* __restrict__ dW1, const float* __restrict__ db1,
    const float* __restrict__ dW2, const float* __restrict__ db2,
    const float* __restrict__ dWr, const float* __restrict__ dbr,
    const float* __restrict__ lng, const float* __restrict__ lnb)
{
    extern __shared__ float sm[];
    float* s_w1t = sm;
    float* s_w2  = sm + 256 * 64;
    float* s_wr  = s_w2 + 256 * 16;
    int tid = threadIdx.x;
    for (int i = tid; i < 64 * 256; i += 256) {
        int j = i >> 8, k = i & 255;
        s_w1t[k * 64 + j] = dW1[i];
    }
    for (int i = tid; i < 256 * 16; i += 256) s_w2[i] = dW2[i];
    for (int i = tid; i < 64 * 16; i += 256)  s_wr[i] = dWr[i];
    __syncthreads();

    int cw = blockIdx.x * 256 + tid;

    float zq[64];
    const float2* cb2 = reinterpret_cast<const float2*>(codebook + (size_t)cw * 64);
#pragma unroll
    for (int j = 0; j < 32; j++) { float2 v = cb2[j]; zq[2 * j] = v.x; zq[2 * j + 1] = v.y; }

    float y[16];
#pragma unroll
    for (int i = 0; i < 16; i++) y[i] = db2[i];
    for (int k = 0; k < 256; k++) {
        const float4* w1c = reinterpret_cast<const float4*>(s_w1t + k * 64);
        float f = db1[k];
#pragma unroll
        for (int j4 = 0; j4 < 16; j4++) {
            float4 w = w1c[j4];
            f += zq[j4 * 4 + 0] * w.x + zq[j4 * 4 + 1] * w.y
               + zq[j4 * 4 + 2] * w.z + zq[j4 * 4 + 3] * w.w;
        }
        f = fmaxf(f, 0.f);
        const float4* w2r = reinterpret_cast<const float4*>(s_w2 + k * 16);
#pragma unroll
        for (int i4 = 0; i4 < 4; i4++) {
            float4 w = w2r[i4];
            y[i4 * 4 + 0] += f * w.x;
            y[i4 * 4 + 1] += f * w.y;
            y[i4 * 4 + 2] += f * w.z;
            y[i4 * 4 + 3] += f * w.w;
        }
    }
#pragma unroll
    for (int i = 0; i < 16; i++) y[i] += dbr[i];
#pragma unroll 8
    for (int j = 0; j < 64; j++) {
        float zj = zq[j];
        const float4* wr4 = reinterpret_cast<const float4*>(s_wr + j * 16);
#pragma unroll
        for (int i4 = 0; i4 < 4; i4++) {
            float4 w = wr4[i4];
            y[i4 * 4 + 0] += zj * w.x;
            y[i4 * 4 + 1] += zj * w.y;
            y[i4 * 4 + 2] += zj * w.z;
            y[i4 * 4 + 3] += zj * w.w;
        }
    }
    float mu = 0.f;
#pragma unroll
    for (int i = 0; i < 16; i++) mu += y[i];
    mu *= (1.0f / 16);
    float var = 0.f;
#pragma unroll
    for (int i = 0; i < 16; i++) { float d = y[i] - mu; var += d * d; }
    var *= (1.0f / 16);
    float rs = 1.0f / sqrtf(var + EPSF);
#pragma unroll
    for (int i = 0; i < 16; i++)
        g_rec[cw * 16 + i] = (y[i] - mu) * rs * lng[i] + lnb[i];
}

// ---------------- kernel 7: gather + denorm + rec-loss ----------------
__global__ __launch_bounds__(256) void pcv_apply(
    const float* __restrict__ x,
    const float* __restrict__ revin_w, const float* __restrict__ revin_b,
    float* __restrict__ out)
{
    __shared__ float s_rec[Kk * PLn];
    __shared__ float red[256];
    int tid = threadIdx.x;
    for (int i = tid; i < Kk * PLn; i += 256) s_rec[i] = g_rec[i];
    __syncthreads();

    int c = tid & 31;
    int rgrp = tid >> 5;
    float rwc = revin_w[c] + 1e-10f;
    float rbc = revin_b[c];
    float local = 0.f;
#pragma unroll 4
    for (int it = 0; it < 16; it++) {
        int row = blockIdx.x * 128 + it * 8 + rgrp;
        int b = row >> 11;
        int l = row & 2047;
        int pp = l >> 4, i = l & 15;
        int n = b * 32 + c;
        int idx = (int)out[OFF_IDX + (size_t)n * 128 + pp];
        float rec = s_rec[idx * 16 + i];
        float rv = (rec - rbc) / rwc * g_std[n] + g_mean[n];
        size_t off = (size_t)row * 32 + c;
        out[OFF_R + off] = rv;
        float dx = x[off] - rv;
        local += dx * dx;
    }
    red[tid] = local;
    __syncthreads();
    for (int s = 128; s > 0; s >>= 1) {
        if (tid < s) red[tid] += red[tid + s];
        __syncthreads();
    }
    if (tid == 0) g_rec_partial[blockIdx.x] = red[0];
}

// ---------------- kernel 8: finalize scalars ----------------
__global__ void pcv_final(float* __restrict__ out)
{
    if (threadIdx.x == 0 && blockIdx.x == 0) {
        float sq = 0.f;
        for (int i = 0; i < 512; i++) sq += g_sq_partial[i];
        float recs = 0.f;
        for (int i = 0; i < 512; i++) recs += g_rec_partial[i];
        float mse = sq * (1.0f / 8388608.0f);
        float cluster = mse + 0.25f * mse;
        float rec_loss = recs * (1.0f / 2097152.0f);
        out[0] = rec_loss + 0.2f * cluster;
        out[1] = rec_loss;
        float tot = 0.f;
        for (int k = 0; k < Kk; k++) tot += (float)g_counts[k];
        float inv = 1.0f / (tot + EPSF);
        float ent = 0.f;
        for (int k = 0; k < Kk; k++) {
            float pr = (float)g_counts[k] * inv;
            ent += pr * logf(pr + EPSF);
        }
        out[OFF_PERP] = expf(-ent);
    }
}

// ---------------- launch ----------------
extern "C" void kernel_launch(void* const* d_in, const int* in_sizes, int n_in,
                              void* d_out, int out_size)
{
    const float* x       = (const float*)d_in[0];
    const float* revin_w = (const float*)d_in[1];
    const float* revin_b = (const float*)d_in[2];
    const float* inp_W   = (const float*)d_in[3];
    const float* inp_b   = (const float*)d_in[4];
    const float* Wq = (const float*)d_in[5];  const float* bq = (const float*)d_in[6];
    const float* Wk = (const float*)d_in[7];  const float* bk = (const float*)d_in[8];
    const float* Wv = (const float*)d_in[9];  const float* bv = (const float*)d_in[10];
    const float* Wo = (const float*)d_in[11]; const float* bo = (const float*)d_in[12];
    const float* ln1_g = (const float*)d_in[13]; const float* ln1_b = (const float*)d_in[14];
    const float* W1 = (const float*)d_in[15]; const float* b1 = (const float*)d_in[16];
    const float* W2 = (const float*)d_in[17]; const float* b2 = (const float*)d_in[18];
    const float* ln2_g = (const float*)d_in[19]; const float* ln2_b = (const float*)d_in[20];
    const float* codebook = (const float*)d_in[21];
    const float* dW1 = (const float*)d_in[22]; const float* db1 = (const float*)d_in[23];
    const float* dW2 = (const float*)d_in[24]; const float* db2 = (const float*)d_in[25];
    const float* dWr = (const float*)d_in[26]; const float* dbr = (const float*)d_in[27];
    const float* dlg = (const float*)d_in[28]; const float* dlb = (const float*)d_in[29];
    float* out = (float*)d_out;

    cudaFuncSetAttribute(pcv_qkvh,  cudaFuncAttributeMaxDynamicSharedMemorySize, QKV_SMEM);
    cudaFuncSetAttribute(pcv_attn,  cudaFuncAttributeMaxDynamicSharedMemorySize, ATT_SMEM);
    cudaFuncSetAttribute(pcv_ffn,   cudaFuncAttributeMaxDynamicSharedMemorySize, FFN_SMEM);
    cudaFuncSetAttribute(pcv_quant, cudaFuncAttributeMaxDynamicSharedMemorySize, QNT_SMEM2);
    cudaFuncSetAttribute(pcv_deccb, cudaFuncAttributeMaxDynamicSharedMemorySize, DEC_SMEM);

    pcv_revin<<<Bn, 256>>>(x);
    pcv_deccb<<<2, 256, DEC_SMEM>>>(codebook, dW1, db1, dW2, db2, dWr, dbr, dlg, dlb);
    pcv_qkvh<<<NTOK / 256, 256, QKV_SMEM>>>(x, revin_w, revin_b, inp_W, inp_b,
                                            Wq, bq, Wk, bk, Wv, bv);
    pcv_attn<<<NSEQ, 256, ATT_SMEM>>>(Wo, bo, ln1_g, ln1_b);
    pcv_ffn<<<NTOK / 128, 128, FFN_SMEM>>>(W1, b1, W2, b2, ln2_g, ln2_b);
    pcv_quant<<<NTOK / 256, 128, QNT_SMEM2>>>(codebook, out);
    pcv_apply<<<512, 256>>>(x, revin_w, revin_b, out);
    pcv_final<<<1, 32>>>(out);
}

// round 10
// speedup vs baseline: 1.3775x; 1.0278x over previous
#include <cuda_runtime.h>
#include <math.h>
#include <stdint.h>

// ---------------- problem constants ----------------
#define Bn   32
#define Ln   2048
#define Cn   32
#define PLn  16
#define Pp   128
#define Dd   64
#define Hh   256
#define Kk   512
#define NSEQ (Bn*Cn)        // 1024
#define NTOK (NSEQ*Pp)      // 131072
#define EPSF 1e-5f

// output layout (flattened reference return tuple, float32)
#define OFF_ZQ   ((size_t)2)
#define OFF_R    (OFF_ZQ + (size_t)NTOK*Dd)            // 8388610
#define OFF_IDX  (OFF_R + (size_t)Bn*Ln*Cn)            // 10485762
#define OFF_PERP (OFF_IDX + (size_t)NTOK)              // 10616834

// ---------------- device scratch ----------------
__device__ float g_mean[NSEQ];
__device__ float g_std[NSEQ];
__device__ float g_h[(size_t)NTOK*Dd];
__device__ float g_q[(size_t)NTOK*Dd];      // q, later reused as hn (post-LN1)
__device__ float g_k[(size_t)NTOK*Dd];
__device__ float g_v[(size_t)NTOK*Dd];
__device__ float g_z[(size_t)NTOK*Dd];
__device__ int   g_counts[Kk];
__device__ float g_sq_partial[512];
__device__ float g_rec_partial[512];
__device__ float g_rec[Kk*PLn];

// ---------------- packed f32x2 helpers ----------------
__device__ __forceinline__ unsigned long long pk2(float lo, float hi)
{
    unsigned long long r;
    asm("mov.b64 %0,{%1,%2};" : "=l"(r) : "f"(lo), "f"(hi));
    return r;
}
__device__ __forceinline__ void upk2(unsigned long long v, float& lo, float& hi)
{
    asm("mov.b64 {%0,%1},%2;" : "=f"(lo), "=f"(hi) : "l"(v));
}
__device__ __forceinline__ unsigned long long fma2_(unsigned long long a,
                                                    unsigned long long b,
                                                    unsigned long long c)
{
    unsigned long long d;
    asm("fma.rn.f32x2 %0,%1,%2,%3;" : "=l"(d) : "l"(a), "l"(b), "l"(c));
    return d;
}
__device__ __forceinline__ float hsum2(unsigned long long v)
{
    float lo, hi;
    upk2(v, lo, hi);
    return lo + hi;
}

// acc2[32] (64 outputs) += hk * wrow[0..63]   — bit-identical to scalar axpy
__device__ __forceinline__ void axpy64_p(unsigned long long* acc2, float hk,
                                         const float* __restrict__ wrow)
{
    unsigned long long hk2 = pk2(hk, hk);
    const ulonglong2* w2 = reinterpret_cast<const ulonglong2*>(wrow);
#pragma unroll
    for (int i = 0; i < 16; i++) {
        ulonglong2 ww = w2[i];
        acc2[2*i]   = fma2_(hk2, ww.x, acc2[2*i]);
        acc2[2*i+1] = fma2_(hk2, ww.y, acc2[2*i+1]);
    }
}
// acc2[16] (32 outputs) += hk * wrow[0..31]
__device__ __forceinline__ void axpy32_p(unsigned long long* acc2, float hk,
                                         const float* __restrict__ wrow)
{
    unsigned long long hk2 = pk2(hk, hk);
    const ulonglong2* w2 = reinterpret_cast<const ulonglong2*>(wrow);
#pragma unroll
    for (int i = 0; i < 8; i++) {
        ulonglong2 ww = w2[i];
        acc2[2*i]   = fma2_(hk2, ww.x, acc2[2*i]);
        acc2[2*i+1] = fma2_(hk2, ww.y, acc2[2*i+1]);
    }
}

// packed 64x64 row-matmul: acc[d] = bias[d] + sum_k hrow[k]*w[k*64+d]
__device__ __forceinline__ void mm64_p(const float* __restrict__ hrow,
                                       const float* __restrict__ w,
                                       const float* __restrict__ bias,
                                       float* acc)
{
    unsigned long long a2[32];
#pragma unroll
    for (int i = 0; i < 32; i++) a2[i] = pk2(bias[2*i], bias[2*i+1]);
#pragma unroll 4
    for (int k = 0; k < 64; k++) axpy64_p(a2, hrow[k], w + k * 64);
#pragma unroll
    for (int i = 0; i < 32; i++) upk2(a2[i], acc[2*i], acc[2*i+1]);
}

__device__ __forceinline__ void store_row64(float* dst, const float* v)
{
    float4* d4 = reinterpret_cast<float4*>(dst);
#pragma unroll
    for (int j = 0; j < 16; j++)
        d4[j] = make_float4(v[4*j], v[4*j+1], v[4*j+2], v[4*j+3]);
}

__device__ __forceinline__ void load_row64(float* v, const float* src)
{
    const float4* s4 = reinterpret_cast<const float4*>(src);
#pragma unroll
    for (int j = 0; j < 16; j++) {
        float4 t = s4[j];
        v[4*j] = t.x; v[4*j+1] = t.y; v[4*j+2] = t.z; v[4*j+3] = t.w;
    }
}

// ---------------- kernel 1: RevIN stats + zero counts ----------------
__global__ __launch_bounds__(256) void pcv_revin(const float* __restrict__ x)
{
    int b = blockIdx.x;
    int t = threadIdx.x;
    int c = t & 31;
    int g = t >> 5;
    if (b == 0) {
        for (int i = t; i < Kk; i += 256) g_counts[i] = 0;
    }
    float s = 0.f, s2 = 0.f;
    const float* xb = x + (size_t)b * Ln * Cn + c;
    for (int l = g; l < Ln; l += 8) {
        float v = xb[(size_t)l * Cn];
        s += v; s2 += v * v;
    }
    __shared__ float sh_s[256], sh_q[256];
    sh_s[t] = s; sh_q[t] = s2;
    __syncthreads();
    if (g == 0) {
        float ss = 0.f, qq = 0.f;
#pragma unroll
        for (int i = 0; i < 8; i++) { ss += sh_s[i * 32 + c]; qq += sh_q[i * 32 + c]; }
        float mean = ss * (1.0f / Ln);
        float var  = qq * (1.0f / Ln) - mean * mean;
        g_mean[b * 32 + c] = mean;
        g_std [b * 32 + c] = sqrtf(var + EPSF);
    }
}

// ---------------- kernel 2: embed + Q/K/V (packed f32x2, unchanged) ----------------
#define QKV_SMEM ((256*65 + 64*64) * 4)

__global__ void __launch_bounds__(256, 2) pcv_qkvh(
    const float* __restrict__ x,
    const float* __restrict__ revin_w, const float* __restrict__ revin_b,
    const float* __restrict__ inp_W,   const float* __restrict__ inp_b,
    const float* __restrict__ Wq, const float* __restrict__ bq,
    const float* __restrict__ Wk, const float* __restrict__ bk,
    const float* __restrict__ Wv, const float* __restrict__ bv)
{
    extern __shared__ float sm[];
    float* s_h = sm;
    float* s_w = sm + 256 * 65;

    int tid = threadIdx.x;
    int t0  = blockIdx.x * 256 + tid;
    int n = t0 >> 7, p = t0 & 127;
    int b = n >> 5, c = n & 31;

    float mean = g_mean[n];
    float istd = 1.0f / g_std[n];
    float rw = revin_w[c], rb = revin_b[c];
    float* hrow = s_h + tid * 65;

    for (int i = tid; i < 16 * 64; i += 256) s_w[i] = inp_W[i];
    __syncthreads();

    float acc[64];
    {
        unsigned long long a2[32];
#pragma unroll
        for (int i = 0; i < 32; i++) a2[i] = pk2(inp_b[2*i], inp_b[2*i+1]);
        const float* xp = x + ((size_t)b * Ln + (size_t)p * PLn) * Cn + c;
#pragma unroll
        for (int j = 0; j < 16; j++) {
            float xv = (xp[(size_t)j * Cn] - mean) * istd * rw + rb;
            axpy64_p(a2, xv, s_w + j * 64);
        }
#pragma unroll
        for (int i = 0; i < 32; i++) upk2(a2[i], acc[2*i], acc[2*i+1]);
    }
#pragma unroll
    for (int d = 0; d < 64; d++) hrow[d] = acc[d];
    store_row64(g_h + (size_t)t0 * 64, acc);
    __syncthreads();

    for (int i = tid; i < 4096; i += 256) s_w[i] = Wq[i];
    __syncthreads();
    mm64_p(hrow, s_w, bq, acc);
    store_row64(g_q + (size_t)t0 * 64, acc);
    __syncthreads();
    for (int i = tid; i < 4096; i += 256) s_w[i] = Wk[i];
    __syncthreads();
    mm64_p(hrow, s_w, bk, acc);
    store_row64(g_k + (size_t)t0 * 64, acc);
    __syncthreads();
    for (int i = tid; i < 4096; i += 256) s_w[i] = Wv[i];
    __syncthreads();
    mm64_p(hrow, s_w, bv, acc);
    store_row64(g_v + (size_t)t0 * 64, acc);
}

// ---------------- kernel 3: attention + Wo + LN1 (packed even/odd score dots) ----------------
#define SKV 68
#define ATT_SMEM ((128*SKV*2) * 4)

__global__ void __launch_bounds__(256, 2) pcv_attn(
    const float* __restrict__ Wo, const float* __restrict__ bo,
    const float* __restrict__ ln1_g, const float* __restrict__ ln1_b)
{
    extern __shared__ float sm[];
    float* s_k = sm;
    float* s_v = sm + 128 * SKV;
    float* s_a = s_k;
    float* s_w = s_v;

    int n = blockIdx.x;
    int tid = threadIdx.x;
    int p  = tid & 127;
    int hp = tid >> 7;
    int h0 = hp * 2;
    int t0 = n * 128 + p;

    const float4* gk = reinterpret_cast<const float4*>(g_k + (size_t)n * 128 * 64);
    const float4* gv = reinterpret_cast<const float4*>(g_v + (size_t)n * 128 * 64);
    for (int e = tid; e < 2048; e += 256) {
        int row = e >> 4, c4 = e & 15;
        *reinterpret_cast<float4*>(s_k + row * SKV + c4 * 4) = gk[e];
        *reinterpret_cast<float4*>(s_v + row * SKV + c4 * 4) = gv[e];
    }
    __syncthreads();

    // q for this thread's 2 heads, packed even/odd
    unsigned long long q02[8], q12[8];
    {
        const float4* qg = reinterpret_cast<const float4*>(g_q + (size_t)t0 * 64 + h0 * 16);
#pragma unroll
        for (int j4 = 0; j4 < 4; j4++) {
            float4 a = qg[j4];
            q02[2*j4]   = pk2(a.x, a.y);
            q02[2*j4+1] = pk2(a.z, a.w);
        }
#pragma unroll
        for (int j4 = 0; j4 < 4; j4++) {
            float4 a = qg[4 + j4];
            q12[2*j4]   = pk2(a.x, a.y);
            q12[2*j4+1] = pk2(a.z, a.w);
        }
    }
    float m0 = -1e30f, l0 = 0.f, m1 = -1e30f, l1 = 0.f;
    float o0[16], o1[16];
#pragma unroll
    for (int j = 0; j < 16; j++) { o0[j] = 0.f; o1[j] = 0.f; }

    for (int pk = 0; pk < 128; pk++) {
        const ulonglong2* kr = reinterpret_cast<const ulonglong2*>(s_k + pk * SKV + h0 * 16);
        unsigned long long s02 = 0ull, s12 = 0ull;
#pragma unroll
        for (int i = 0; i < 4; i++) {
            ulonglong2 kk = kr[i];
            s02 = fma2_(q02[2*i],   kk.x, s02);
            s02 = fma2_(q02[2*i+1], kk.y, s02);
        }
#pragma unroll
        for (int i = 0; i < 4; i++) {
            ulonglong2 kk = kr[4 + i];
            s12 = fma2_(q12[2*i],   kk.x, s12);
            s12 = fma2_(q12[2*i+1], kk.y, s12);
        }
        float s0 = hsum2(s02) * 0.25f;
        float s1 = hsum2(s12) * 0.25f;
        float mn0 = fmaxf(m0, s0), mn1 = fmaxf(m1, s1);
        float c0 = __expf(m0 - mn0), c1 = __expf(m1 - mn1);
        float w0 = __expf(s0 - mn0), w1 = __expf(s1 - mn1);
        l0 = l0 * c0 + w0;
        l1 = l1 * c1 + w1;
        const float4* vr = reinterpret_cast<const float4*>(s_v + pk * SKV + h0 * 16);
#pragma unroll
        for (int j4 = 0; j4 < 4; j4++) {
            float4 vv = vr[j4];
            o0[j4*4+0] = o0[j4*4+0] * c0 + w0 * vv.x;
            o0[j4*4+1] = o0[j4*4+1] * c0 + w0 * vv.y;
            o0[j4*4+2] = o0[j4*4+2] * c0 + w0 * vv.z;
            o0[j4*4+3] = o0[j4*4+3] * c0 + w0 * vv.w;
        }
#pragma unroll
        for (int j4 = 0; j4 < 4; j4++) {
            float4 vv = vr[4 + j4];
            o1[j4*4+0] = o1[j4*4+0] * c1 + w1 * vv.x;
            o1[j4*4+1] = o1[j4*4+1] * c1 + w1 * vv.y;
            o1[j4*4+2] = o1[j4*4+2] * c1 + w1 * vv.z;
            o1[j4*4+3] = o1[j4*4+3] * c1 + w1 * vv.w;
        }
        m0 = mn0; m1 = mn1;
    }
    float inv0 = 1.0f / l0, inv1 = 1.0f / l1;
    __syncthreads();

    {
        float* ar = s_a + p * 65 + hp * 32;
#pragma unroll
        for (int j = 0; j < 16; j++) ar[j]      = o0[j] * inv0;
#pragma unroll
        for (int j = 0; j < 16; j++) ar[16 + j] = o1[j] * inv1;
    }
    for (int i = tid; i < 4096; i += 256) s_w[i] = Wo[i];
    __syncthreads();

    int dlo = hp * 32;
    float acch[32];
    {
        unsigned long long a2[16];
#pragma unroll
        for (int i = 0; i < 16; i++) a2[i] = pk2(bo[dlo + 2*i], bo[dlo + 2*i + 1]);
        const float* ar = s_a + p * 65;
#pragma unroll 4
        for (int k = 0; k < 64; k++) axpy32_p(a2, ar[k], s_w + k * 64 + dlo);
#pragma unroll
        for (int i = 0; i < 16; i++) upk2(a2[i], acch[2*i], acch[2*i+1]);
    }
    __syncthreads();
    {
        float* ac = s_a + p * 65 + dlo;
#pragma unroll
        for (int j = 0; j < 32; j++) ac[j] = acch[j];
    }
    __syncthreads();

    if (hp == 0) {
        float hreg[64];
        load_row64(hreg, g_h + (size_t)t0 * 64);
        const float* ac = s_a + p * 65;
        float msum = 0.f;
#pragma unroll
        for (int d = 0; d < 64; d++) { hreg[d] = hreg[d] + ac[d]; msum += hreg[d]; }
        float mu = msum * (1.0f / 64);
        float vs = 0.f;
#pragma unroll
        for (int d = 0; d < 64; d++) { float df = hreg[d] - mu; vs += df * df; }
        float rs = 1.0f / sqrtf(vs * (1.0f / 64) + EPSF);
#pragma unroll
        for (int d = 0; d < 64; d++) hreg[d] = (hreg[d] - mu) * rs * ln1_g[d] + ln1_b[d];
        store_row64(g_q + (size_t)t0 * 64, hreg);
    }
}

// ---------------- kernel 4: FFN (packed even/odd W1 dots + packed W2 axpy) ----------------
#define FFN_SMEM ((128*64*2) * 4)

__global__ void __launch_bounds__(128, 3) pcv_ffn(
    const float* __restrict__ W1, const float* __restrict__ b1,
    const float* __restrict__ W2, const float* __restrict__ b2,
    const float* __restrict__ ln2_g, const float* __restrict__ ln2_b)
{
    extern __shared__ float sm[];
    float* s_w1t = sm;
    float* s_w2  = sm + 128 * 64;

    int tid = threadIdx.x;
    int t = blockIdx.x * 128 + tid;

    // hn packed even/odd (hn floats recovered at the end)
    unsigned long long hn2[32];
    {
        const float4* s4 = reinterpret_cast<const float4*>(g_q + (size_t)t * 64);
#pragma unroll
        for (int j = 0; j < 16; j++) {
            float4 v = s4[j];
            hn2[2*j]   = pk2(v.x, v.y);
            hn2[2*j+1] = pk2(v.z, v.w);
        }
    }

    unsigned long long acc2[32];
#pragma unroll
    for (int i = 0; i < 32; i++) acc2[i] = pk2(b2[2*i], b2[2*i+1]);

    for (int h = 0; h < 2; h++) {
        if (h) __syncthreads();
        for (int i = tid; i < 128 * 64; i += 128) {
            int kk = i >> 6, j = i & 63;
            s_w1t[i] = W1[j * 256 + h * 128 + kk];
        }
        for (int i = tid; i < 128 * 64; i += 128) s_w2[i] = W2[h * 8192 + i];
        __syncthreads();
        for (int k = 0; k < 128; k += 4) {
            unsigned long long f02 = pk2(b1[h*128 + k + 0], 0.f);
            unsigned long long f12 = pk2(b1[h*128 + k + 1], 0.f);
            unsigned long long f22 = pk2(b1[h*128 + k + 2], 0.f);
            unsigned long long f32 = pk2(b1[h*128 + k + 3], 0.f);
            const ulonglong2* c0 = reinterpret_cast<const ulonglong2*>(s_w1t + (k + 0) * 64);
            const ulonglong2* c1 = reinterpret_cast<const ulonglong2*>(s_w1t + (k + 1) * 64);
            const ulonglong2* c2 = reinterpret_cast<const ulonglong2*>(s_w1t + (k + 2) * 64);
            const ulonglong2* c3 = reinterpret_cast<const ulonglong2*>(s_w1t + (k + 3) * 64);
#pragma unroll
            for (int i = 0; i < 16; i++) {
                ulonglong2 w0 = c0[i], w1 = c1[i], w2 = c2[i], w3 = c3[i];
                unsigned long long ha = hn2[2*i], hb = hn2[2*i+1];
                f02 = fma2_(ha, w0.x, f02); f02 = fma2_(hb, w0.y, f02);
                f12 = fma2_(ha, w1.x, f12); f12 = fma2_(hb, w1.y, f12);
                f22 = fma2_(ha, w2.x, f22); f22 = fma2_(hb, w2.y, f22);
                f32 = fma2_(ha, w3.x, f32); f32 = fma2_(hb, w3.y, f32);
            }
            float f0 = fmaxf(hsum2(f02), 0.f);
            float f1 = fmaxf(hsum2(f12), 0.f);
            float f2 = fmaxf(hsum2(f22), 0.f);
            float f3 = fmaxf(hsum2(f32), 0.f);
            axpy64_p(acc2, f0, s_w2 + (k + 0) * 64);
            axpy64_p(acc2, f1, s_w2 + (k + 1) * 64);
            axpy64_p(acc2, f2, s_w2 + (k + 2) * 64);
            axpy64_p(acc2, f3, s_w2 + (k + 3) * 64);
        }
    }

    float acc[64], hn[64];
#pragma unroll
    for (int i = 0; i < 32; i++) upk2(acc2[i], acc[2*i], acc[2*i+1]);
#pragma unroll
    for (int i = 0; i < 32; i++) upk2(hn2[i], hn[2*i], hn[2*i+1]);

    float msum = 0.f;
#pragma unroll
    for (int d = 0; d < 64; d++) { acc[d] += hn[d]; msum += acc[d]; }
    float mu = msum * (1.0f / 64);
    float vs = 0.f;
#pragma unroll
    for (int d = 0; d < 64; d++) { float df = acc[d] - mu; vs += df * df; }
    float rs = 1.0f / sqrtf(vs * (1.0f / 64) + EPSF);
    float zr[64];
#pragma unroll
    for (int d = 0; d < 64; d++) zr[d] = (acc[d] - mu) * rs * ln2_g[d] + ln2_b[d];
    store_row64(g_z + (size_t)t * 64, zr);
}

// ---------------- kernel 5: quantizer (packed even/odd dots, 2 tokens/thread) ----------------
#define QNT_SMEM2 ((128*64 + 128) * 4)

__global__ void __launch_bounds__(128, 3) pcv_quant(const float* __restrict__ codebook,
                                                    float* __restrict__ out)
{
    extern __shared__ float sm[];
    float* s_cb = sm;
    float* s_e2 = sm + 128 * 64;
    __shared__ float red[128];
    int tid = threadIdx.x;
    int tA = blockIdx.x * 256 + tid;
    int tB = tA + 128;

    float zA[64], zB[64];
    load_row64(zA, g_z + (size_t)tA * 64);
    load_row64(zB, g_z + (size_t)tB * 64);
    float z2A = 0.f, z2B = 0.f;
#pragma unroll
    for (int j = 0; j < 64; j++) z2A += zA[j] * zA[j];
#pragma unroll
    for (int j = 0; j < 64; j++) z2B += zB[j] * zB[j];

    unsigned long long zA2[32], zB2[32];
#pragma unroll
    for (int i = 0; i < 32; i++) zA2[i] = pk2(zA[2*i], zA[2*i+1]);
#pragma unroll
    for (int i = 0; i < 32; i++) zB2[i] = pk2(zB[2*i], zB[2*i+1]);

    float bestA = 3.4e38f, bestB = 3.4e38f;
    int biA = 0, biB = 0;

    for (int cch = 0; cch < 4; cch++) {
        if (cch) __syncthreads();
        for (int i = tid; i < 128 * 64; i += 128) s_cb[i] = codebook[cch * 8192 + i];
        __syncthreads();
        {
            const float* cr = s_cb + tid * 64;
            float s = 0.f;
#pragma unroll 8
            for (int j = 0; j < 64; j++) s += cr[j] * cr[j];
            s_e2[tid] = s;
        }
        __syncthreads();
        for (int kk = 0; kk < 128; kk += 2) {
            const ulonglong2* c0 = reinterpret_cast<const ulonglong2*>(s_cb + kk * 64);
            const ulonglong2* c1 = reinterpret_cast<const ulonglong2*>(s_cb + (kk + 1) * 64);
            unsigned long long a0 = 0ull, b0 = 0ull, a1 = 0ull, b1 = 0ull;
#pragma unroll
            for (int i = 0; i < 16; i++) {
                ulonglong2 cc0 = c0[i];
                ulonglong2 cc1 = c1[i];
                unsigned long long za = zA2[2*i], zb = zA2[2*i+1];
                unsigned long long wa = zB2[2*i], wb = zB2[2*i+1];
                a0 = fma2_(za, cc0.x, a0); a0 = fma2_(zb, cc0.y, a0);
                b0 = fma2_(wa, cc0.x, b0); b0 = fma2_(wb, cc0.y, b0);
                a1 = fma2_(za, cc1.x, a1); a1 = fma2_(zb, cc1.y, a1);
                b1 = fma2_(wa, cc1.x, b1); b1 = fma2_(wb, cc1.y, b1);
            }
            float dA0 = hsum2(a0);
            float dB0 = hsum2(b0);
            float dA1 = hsum2(a1);
            float dB1 = hsum2(b1);
            float e20 = s_e2[kk], e21 = s_e2[kk + 1];
            int kg = cch * 128 + kk;
            float d0A = __fadd_rn(__fadd_rn(z2A, e20), -__fmul_rn(2.0f, dA0));
            float d0B = __fadd_rn(__fadd_rn(z2B, e20), -__fmul_rn(2.0f, dB0));
            if (d0A < bestA) { bestA = d0A; biA = kg; }
            if (d0B < bestB) { bestB = d0B; biB = kg; }
            float d1A = __fadd_rn(__fadd_rn(z2A, e21), -__fmul_rn(2.0f, dA1));
            float d1B = __fadd_rn(__fadd_rn(z2B, e21), -__fmul_rn(2.0f, dB1));
            if (d1A < bestA) { bestA = d1A; biA = kg + 1; }
            if (d1B < bestB) { bestB = d1B; biB = kg + 1; }
        }
    }

    {
        float2* zqo = reinterpret_cast<float2*>(out + OFF_ZQ + (size_t)tA * 64);
        const float2* cb2 = reinterpret_cast<const float2*>(codebook + (size_t)biA * 64);
#pragma unroll
        for (int j = 0; j < 32; j++) zqo[j] = cb2[j];
    }
    {
        float2* zqo = reinterpret_cast<float2*>(out + OFF_ZQ + (size_t)tB * 64);
        const float2* cb2 = reinterpret_cast<const float2*>(codebook + (size_t)biB * 64);
#pragma unroll
        for (int j = 0; j < 32; j++) zqo[j] = cb2[j];
    }
    out[OFF_IDX + tA] = (float)biA;
    out[OFF_IDX + tB] = (float)biB;
    atomicAdd(&g_counts[biA], 1);
    atomicAdd(&g_counts[biB], 1);

    red[tid] = bestA + bestB;
    __syncthreads();
    for (int s = 64; s > 0; s >>= 1) {
        if (tid < s) red[tid] += red[tid + s];
        __syncthreads();
    }
    if (tid == 0) g_sq_partial[blockIdx.x] = red[0];
}

// ---------------- kernel 6: decode the 512 codewords once ----------------
#define DEC_SMEM ((256*64 + 256*16 + 64*16) * 4)

__global__ __launch_bounds__(256) void pcv_deccb(
    const float* __restrict__ codebook,
    const float* __restrict__ dW1, const float* __restrict__ db1,
    const float* __restrict__ dW2, const float* __restrict__ db2,
    const float* __restrict__ dWr, const float* __restrict__ dbr,
    const float* __restrict__ lng, const float* __restrict__ lnb)
{
    extern __shared__ float sm[];
    float* s_w1t = sm;
    float* s_w2  = sm + 256 * 64;
    float* s_wr  = s_w2 + 256 * 16;
    int tid = threadIdx.x;
    for (int i = tid; i < 64 * 256; i += 256) {
        int j = i >> 8, k = i & 255;
        s_w1t[k * 64 + j] = dW1[i];
    }
    for (int i = tid; i < 256 * 16; i += 256) s_w2[i] = dW2[i];
    for (int i = tid; i < 64 * 16; i += 256)  s_wr[i] = dWr[i];
    __syncthreads();

    int cw = blockIdx.x * 256 + tid;

    float zq[64];
    const float2* cb2 = reinterpret_cast<const float2*>(codebook + (size_t)cw * 64);
#pragma unroll
    for (int j = 0; j < 32; j++) { float2 v = cb2[j]; zq[2 * j] = v.x; zq[2 * j + 1] = v.y; }

    float y[16];
#pragma unroll
    for (int i = 0; i < 16; i++) y[i] = db2[i];
    for (int k = 0; k < 256; k++) {
        const float4* w1c = reinterpret_cast<const float4*>(s_w1t + k * 64);
        float f = db1[k];
#pragma unroll
        for (int j4 = 0; j4 < 16; j4++) {
            float4 w = w1c[j4];
            f += zq[j4 * 4 + 0] * w.x + zq[j4 * 4 + 1] * w.y
               + zq[j4 * 4 + 2] * w.z + zq[j4 * 4 + 3] * w.w;
        }
        f = fmaxf(f, 0.f);
        const float4* w2r = reinterpret_cast<const float4*>(s_w2 + k * 16);
#pragma unroll
        for (int i4 = 0; i4 < 4; i4++) {
            float4 w = w2r[i4];
            y[i4 * 4 + 0] += f * w.x;
            y[i4 * 4 + 1] += f * w.y;
            y[i4 * 4 + 2] += f * w.z;
            y[i4 * 4 + 3] += f * w.w;
        }
    }
#pragma unroll
    for (int i = 0; i < 16; i++) y[i] += dbr[i];
#pragma unroll 8
    for (int j = 0; j < 64; j++) {
        float zj = zq[j];
        const float4* wr4 = reinterpret_cast<const float4*>(s_wr + j * 16);
#pragma unroll
        for (int i4 = 0; i4 < 4; i4++) {
            float4 w = wr4[i4];
            y[i4 * 4 + 0] += zj * w.x;
            y[i4 * 4 + 1] += zj * w.y;
            y[i4 * 4 + 2] += zj * w.z;
            y[i4 * 4 + 3] += zj * w.w;
        }
    }
    float mu = 0.f;
#pragma unroll
    for (int i = 0; i < 16; i++) mu += y[i];
    mu *= (1.0f / 16);
    float var = 0.f;
#pragma unroll
    for (int i = 0; i < 16; i++) { float d = y[i] - mu; var += d * d; }
    var *= (1.0f / 16);
    float rs = 1.0f / sqrtf(var + EPSF);
#pragma unroll
    for (int i = 0; i < 16; i++)
        g_rec[cw * 16 + i] = (y[i] - mu) * rs * lng[i] + lnb[i];
}

// ---------------- kernel 7: gather + denorm + rec-loss ----------------
__global__ __launch_bounds__(256) void pcv_apply(
    const float* __restrict__ x,
    const float* __restrict__ revin_w, const float* __restrict__ revin_b,
    float* __restrict__ out)
{
    __shared__ float s_rec[Kk * PLn];
    __shared__ float red[256];
    int tid = threadIdx.x;
    for (int i = tid; i < Kk * PLn; i += 256) s_rec[i] = g_rec[i];
    __syncthreads();

    int c = tid & 31;
    int rgrp = tid >> 5;
    float rwc = revin_w[c] + 1e-10f;
    float rbc = revin_b[c];
    float local = 0.f;
#pragma unroll 4
    for (int it = 0; it < 16; it++) {
        int row = blockIdx.x * 128 + it * 8 + rgrp;
        int b = row >> 11;
        int l = row & 2047;
        int pp = l >> 4, i = l & 15;
        int n = b * 32 + c;
        int idx = (int)out[OFF_IDX + (size_t)n * 128 + pp];
        float rec = s_rec[idx * 16 + i];
        float rv = (rec - rbc) / rwc * g_std[n] + g_mean[n];
        size_t off = (size_t)row * 32 + c;
        out[OFF_R + off] = rv;
        float dx = x[off] - rv;
        local += dx * dx;
    }
    red[tid] = local;
    __syncthreads();
    for (int s = 128; s > 0; s >>= 1) {
        if (tid < s) red[tid] += red[tid + s];
        __syncthreads();
    }
    if (tid == 0) g_rec_partial[blockIdx.x] = red[0];
}

// ---------------- kernel 8: finalize scalars ----------------
__global__ void pcv_final(float* __restrict__ out)
{
    if (threadIdx.x == 0 && blockIdx.x == 0) {
        float sq = 0.f;
        for (int i = 0; i < 512; i++) sq += g_sq_partial[i];
        float recs = 0.f;
        for (int i = 0; i < 512; i++) recs += g_rec_partial[i];
        float mse = sq * (1.0f / 8388608.0f);
        float cluster = mse + 0.25f * mse;
        float rec_loss = recs * (1.0f / 2097152.0f);
        out[0] = rec_loss + 0.2f * cluster;
        out[1] = rec_loss;
        float tot = 0.f;
        for (int k = 0; k < Kk; k++) tot += (float)g_counts[k];
        float inv = 1.0f / (tot + EPSF);
        float ent = 0.f;
        for (int k = 0; k < Kk; k++) {
            float pr = (float)g_counts[k] * inv;
            ent += pr * logf(pr + EPSF);
        }
        out[OFF_PERP] = expf(-ent);
    }
}

// ---------------- launch ----------------
extern "C" void kernel_launch(void* const* d_in, const int* in_sizes, int n_in,
                              void* d_out, int out_size)
{
    const float* x       = (const float*)d_in[0];
    const float* revin_w = (const float*)d_in[1];
    const float* revin_b = (const float*)d_in[2];
    const float* inp_W   = (const float*)d_in[3];
    const float* inp_b   = (const float*)d_in[4];
    const float* Wq = (const float*)d_in[5];  const float* bq = (const float*)d_in[6];
    const float* Wk = (const float*)d_in[7];  const float* bk = (const float*)d_in[8];
    const float* Wv = (const float*)d_in[9];  const float* bv = (const float*)d_in[10];
    const float* Wo = (const float*)d_in[11]; const float* bo = (const float*)d_in[12];
    const float* ln1_g = (const float*)d_in[13]; const float* ln1_b = (const float*)d_in[14];
    const float* W1 = (const float*)d_in[15]; const float* b1 = (const float*)d_in[16];
    const float* W2 = (const float*)d_in[17]; const float* b2 = (const float*)d_in[18];
    const float* ln2_g = (const float*)d_in[19]; const float* ln2_b = (const float*)d_in[20];
    const float* codebook = (const float*)d_in[21];
    const float* dW1 = (const float*)d_in[22]; const float* db1 = (const float*)d_in[23];
    const float* dW2 = (const float*)d_in[24]; const float* db2 = (const float*)d_in[25];
    const float* dWr = (const float*)d_in[26]; const float* dbr = (const float*)d_in[27];
    const float* dlg = (const float*)d_in[28]; const float* dlb = (const float*)d_in[29];
    float* out = (float*)d_out;

    cudaFuncSetAttribute(pcv_qkvh,  cudaFuncAttributeMaxDynamicSharedMemorySize, QKV_SMEM);
    cudaFuncSetAttribute(pcv_attn,  cudaFuncAttributeMaxDynamicSharedMemorySize, ATT_SMEM);
    cudaFuncSetAttribute(pcv_ffn,   cudaFuncAttributeMaxDynamicSharedMemorySize, FFN_SMEM);
    cudaFuncSetAttribute(pcv_quant, cudaFuncAttributeMaxDynamicSharedMemorySize, QNT_SMEM2);
    cudaFuncSetAttribute(pcv_deccb, cudaFuncAttributeMaxDynamicSharedMemorySize, DEC_SMEM);

    pcv_revin<<<Bn, 256>>>(x);
    pcv_deccb<<<2, 256, DEC_SMEM>>>(codebook, dW1, db1, dW2, db2, dWr, dbr, dlg, dlb);
    pcv_qkvh<<<NTOK / 256, 256, QKV_SMEM>>>(x, revin_w, revin_b, inp_W, inp_b,
                                            Wq, bq, Wk, bk, Wv, bv);
    pcv_attn<<<NSEQ, 256, ATT_SMEM>>>(Wo, bo, ln1_g, ln1_b);
    pcv_ffn<<<NTOK / 128, 128, FFN_SMEM>>>(W1, b1, W2, b2, ln2_g, ln2_b);
    pcv_quant<<<NTOK / 256, 128, QNT_SMEM2>>>(codebook, out);
    pcv_apply<<<512, 256>>>(x, revin_w, revin_b, out);
    pcv_final<<<1, 32>>>(out);
}